// round 9
// baseline (speedup 1.0000x reference)
#include <cuda_runtime.h>
#include <cuda_bf16.h>
#include <math.h>

#define BB   8
#define TT   2048
#define DIN  1024
#define HH   64
#define BT   (BB*TT)
#define PST  36      // smem row stride in u32 (144B) -> conflict-free ldmatrix

typedef unsigned int u32;

// Packed bf16x2 hi/lo scratch (q,k,v) and prepped weights/inputs.
__device__ __align__(16) u32 g_qh[BT*32];
__device__ __align__(16) u32 g_ql[BT*32];
__device__ __align__(16) u32 g_kh[BT*32];
__device__ __align__(16) u32 g_kl[BT*32];
__device__ __align__(16) u32 g_vh[BT*32];
__device__ __align__(16) u32 g_vl[BT*32];
// V transposed for attention: [b][h 0..63][sp 0..1023]
__device__ __align__(16) u32 g_vth[BB*64*1024];
__device__ __align__(16) u32 g_vtl[BB*64*1024];
// W fragment-ready: [n 0..191][kk 0..511] u32 = pack(W[2kk][n], W[2kk+1][n])
__device__ __align__(16) u32 g_wh[192*512];
__device__ __align__(16) u32 g_wl[192*512];
// X fragment-ready: [row 0..16383][kk 0..511] u32 = pack(x[row][2kk], x[row][2kk+1])
__device__ __align__(16) u32 g_xh[(size_t)BT*512];
__device__ __align__(16) u32 g_xl[(size_t)BT*512];

// ---- helpers ---------------------------------------------------------------
__device__ __forceinline__ u32 pkbf(float lo, float hi) {
    u32 r; asm("cvt.rn.bf16x2.f32 %0, %1, %2;" : "=r"(r) : "f"(hi), "f"(lo));
    return r;
}
__device__ __forceinline__ float bfh(float x) {
    return __bfloat162float(__float2bfloat16(x));
}
__device__ __forceinline__ void mma16816(float* c, const u32* a, const u32* b) {
    asm volatile(
        "mma.sync.aligned.m16n8k16.row.col.f32.bf16.bf16.f32 "
        "{%0,%1,%2,%3}, {%4,%5,%6,%7}, {%8,%9}, {%0,%1,%2,%3};"
        : "+f"(c[0]), "+f"(c[1]), "+f"(c[2]), "+f"(c[3])
        : "r"(a[0]), "r"(a[1]), "r"(a[2]), "r"(a[3]), "r"(b[0]), "r"(b[1]));
}
__device__ __forceinline__ void ldm_x4(u32* r, u32 addr) {
    asm volatile("ldmatrix.sync.aligned.m8n8.x4.shared.b16 {%0,%1,%2,%3}, [%4];"
        : "=r"(r[0]), "=r"(r[1]), "=r"(r[2]), "=r"(r[3]) : "r"(addr));
}
__device__ __forceinline__ void ldm_x2(u32* r, u32 addr) {
    asm volatile("ldmatrix.sync.aligned.m8n8.x2.shared.b16 {%0,%1}, [%2];"
        : "=r"(r[0]), "=r"(r[1]) : "r"(addr));
}
__device__ __forceinline__ void cp16(u32 smem, const void* g) {
    asm volatile("cp.async.cg.shared.global [%0], [%1], 16;" :: "r"(smem), "l"(g));
}
__device__ __forceinline__ void cp_commit() {
    asm volatile("cp.async.commit_group;" ::: "memory");
}
__device__ __forceinline__ void cp_wait0() {
    asm volatile("cp.async.wait_group 0;" ::: "memory");
}
__device__ __forceinline__ u32 smem_u32(const void* p) {
    u32 a;
    asm("{ .reg .u64 t; cvta.to.shared.u64 t, %1; cvt.u32.u64 %0, t; }"
        : "=r"(a) : "l"(p));
    return a;
}

// ---------------------------------------------------------------------------
// Prep: W -> bf16 hi/lo packed, fragment-ready.
// ---------------------------------------------------------------------------
__global__ __launch_bounds__(256) void prep_w_kernel(
    const float* __restrict__ Wq, const float* __restrict__ Wk,
    const float* __restrict__ Wv)
{
    int idx = blockIdx.x * 256 + threadIdx.x;
    int n = idx % 192, kk = idx / 192;
    const float* W = (n < 64) ? Wq : ((n < 128) ? Wk : Wv);
    int col = n & 63;
    float w0 = W[(size_t)(2 * kk) * HH + col];
    float w1 = W[(size_t)(2 * kk + 1) * HH + col];
    float h0 = bfh(w0), h1 = bfh(w1);
    g_wh[n * 512 + kk] = pkbf(h0, h1);
    g_wl[n * 512 + kk] = pkbf(w0 - h0, w1 - h1);
}

// ---------------------------------------------------------------------------
// Prep: X -> bf16 hi/lo packed, fragment-ready. 2M threads.
// ---------------------------------------------------------------------------
__global__ __launch_bounds__(256) void prep_x_kernel(const float* __restrict__ x)
{
    int idx = blockIdx.x * 256 + threadIdx.x;    // 16384*128 tasks
    int row = idx >> 7;
    int kq4 = (idx & 127) << 2;                  // kk base, 4 u32 per thread
    const float* src = x + (size_t)row * DIN + kq4 * 2;
    float4 a = *(const float4*)src;
    float4 b = *(const float4*)(src + 4);
    float ha0 = bfh(a.x), ha1 = bfh(a.y), ha2 = bfh(a.z), ha3 = bfh(a.w);
    float hb0 = bfh(b.x), hb1 = bfh(b.y), hb2 = bfh(b.z), hb3 = bfh(b.w);
    uint4 h, l;
    h.x = pkbf(ha0, ha1); h.y = pkbf(ha2, ha3);
    h.z = pkbf(hb0, hb1); h.w = pkbf(hb2, hb3);
    l.x = pkbf(a.x - ha0, a.y - ha1); l.y = pkbf(a.z - ha2, a.w - ha3);
    l.z = pkbf(b.x - hb0, b.y - hb1); l.w = pkbf(b.z - hb2, b.w - hb3);
    *(uint4*)&g_xh[(size_t)row * 512 + kq4] = h;
    *(uint4*)&g_xl[(size_t)row * 512 + kq4] = l;
}

// ---------------------------------------------------------------------------
// Staging helpers (cp.async, 16B chunks into PST-strided smem).
// ---------------------------------------------------------------------------
__device__ __forceinline__ void stage64(u32 sbyte, const u32* g, int gstride, int tid) {
    #pragma unroll
    for (int u = 0; u < 2; u++) {
        int idx = tid + u * 256;      // 512 16B chunks
        int row = idx >> 3, ch = idx & 7;
        cp16(sbyte + (u32)(row * PST + ch * 4) * 4, g + (size_t)row * gstride + ch * 4);
    }
}
__device__ __forceinline__ void stage192(u32 sbyte, const u32* g, int tid) {
    #pragma unroll
    for (int u = 0; u < 6; u++) {
        int idx = tid + u * 256;      // 1536 16B chunks
        int row = idx >> 3, ch = idx & 7;
        cp16(sbyte + (u32)(row * PST + ch * 4) * 4, g + (size_t)row * 512 + ch * 4);
    }
}

// ---------------------------------------------------------------------------
// Fused QKV projection: pure cp.async double-buffered GEMM (bf16x3, ldmatrix).
// buf layout (u32): XH 0 | XL 2304 | WH 4608 | WL 11520 ; buf stride 18432.
// ---------------------------------------------------------------------------
#define PBUF 18432
#define PROJ_SMEM_U32 (2*PBUF)   // 147456 B

__global__ __launch_bounds__(256) void proj_kernel()
{
    extern __shared__ u32 sm[];
    const u32 sbx = smem_u32(sm);
    const int tid  = threadIdx.x;
    const int wid  = tid >> 5, lane = tid & 31;
    const int slab = wid >> 1, half = wid & 1;
    const int rr   = lane >> 2, q = lane & 3;
    const int m0   = blockIdx.x * 64;

    const int lane7 = lane & 7;
    const int arow  = lane7 + (lane & 8);
    const int acx4  = (lane & 16) ? 16 : 0;
    const int bex4  = (lane & 8) ? 16 : 0;

    // stage chunk 0 into buf 0
    stage64 (sbx + 0 * 4,      g_xh + (size_t)m0 * 512, 512, tid);
    stage64 (sbx + 2304 * 4,   g_xl + (size_t)m0 * 512, 512, tid);
    stage192(sbx + 4608 * 4,   g_wh, tid);
    stage192(sbx + 11520 * 4,  g_wl, tid);
    cp_commit();

    float acc[12][4];
    #pragma unroll
    for (int i = 0; i < 12; i++)
        #pragma unroll
        for (int j = 0; j < 4; j++) acc[i][j] = 0.f;

    for (int c = 0; c < 16; c++) {
        const int buf = c & 1;
        cp_wait0();
        __syncthreads();
        if (c < 15) {
            const u32 nb = (u32)((buf ^ 1) * PBUF) * 4;
            const int kk = (c + 1) * 32;
            stage64 (sbx + nb,             g_xh + (size_t)m0 * 512 + kk, 512, tid);
            stage64 (sbx + nb + 2304 * 4,  g_xl + (size_t)m0 * 512 + kk, 512, tid);
            stage192(sbx + nb + 4608 * 4,  g_wh + kk, tid);
            stage192(sbx + nb + 11520 * 4, g_wl + kk, tid);
            cp_commit();
        }
        const u32 base = (u32)(buf * PBUF);
        const u32 aH = sbx + (base + (slab * 16 + arow) * PST) * 4 + acx4;
        const u32 aL = aH + 2304 * 4;
        const u32 bH = sbx + (base + 4608 + (half * 96 + lane7) * PST) * 4 + bex4;
        const u32 bL = bH + 6912 * 4;

        #pragma unroll
        for (int kt = 0; kt < 4; kt++) {
            u32 ah[4], al[4];
            ldm_x4(ah, aH + kt * 32);
            ldm_x4(al, aL + kt * 32);
            #pragma unroll
            for (int nt = 0; nt < 12; nt++) {
                u32 bh[2], bl[2];
                ldm_x2(bh, bH + nt * (8 * PST * 4) + kt * 32);
                ldm_x2(bl, bL + nt * (8 * PST * 4) + kt * 32);
                mma16816(acc[nt], ah, bh);
                mma16816(acc[nt], ah, bl);
                mma16816(acc[nt], al, bh);
            }
        }
    }

    // epilogue: split to bf16 hi/lo packed q/k/v; fold 0.125 into K
    u32* const GH[3] = {g_qh, g_kh, g_vh};
    u32* const GL[3] = {g_ql, g_kl, g_vl};
    const int row0 = m0 + slab * 16 + rr;
    #pragma unroll
    for (int nt = 0; nt < 12; nt++) {
        int colb = half * 96 + nt * 8;
        int mat = colb >> 6;
        int hqb = (colb & 63) >> 1;
        float s = (mat == 1) ? 0.125f : 1.f;
        float a0 = acc[nt][0] * s, a1 = acc[nt][1] * s;
        float a2 = acc[nt][2] * s, a3 = acc[nt][3] * s;
        float h0 = bfh(a0), h1 = bfh(a1), h2 = bfh(a2), h3 = bfh(a3);
        GH[mat][(size_t)row0 * 32 + hqb + q]       = pkbf(h0, h1);
        GL[mat][(size_t)row0 * 32 + hqb + q]       = pkbf(a0 - h0, a1 - h1);
        GH[mat][(size_t)(row0 + 8) * 32 + hqb + q] = pkbf(h2, h3);
        GL[mat][(size_t)(row0 + 8) * 32 + hqb + q] = pkbf(a2 - h2, a3 - h3);
    }
}

// ---------------------------------------------------------------------------
// V transpose: g_vh/g_vl -> g_vth/g_vtl ([b][h][s-pair]).
// ---------------------------------------------------------------------------
__global__ __launch_bounds__(256) void vt_kernel()
{
    int idx = blockIdx.x * 256 + threadIdx.x;
    int b  = idx >> 15;
    int r  = idx & 32767;
    int hq = r >> 10;
    int sp = r & 1023;
    const u32* vh = g_vh + (size_t)b * TT * 32;
    const u32* vl = g_vl + (size_t)b * TT * 32;
    u32 a = vh[(size_t)(2 * sp) * 32 + hq];
    u32 c = vh[(size_t)(2 * sp + 1) * 32 + hq];
    size_t ob = ((size_t)b * 64 + 2 * hq) * 1024 + sp;
    g_vth[ob]        = __byte_perm(a, c, 0x5410);
    g_vth[ob + 1024] = __byte_perm(a, c, 0x7632);
    a = vl[(size_t)(2 * sp) * 32 + hq];
    c = vl[(size_t)(2 * sp + 1) * 32 + hq];
    g_vtl[ob]        = __byte_perm(a, c, 0x5410);
    g_vtl[ob + 1024] = __byte_perm(a, c, 0x7632);
}

// ---------------------------------------------------------------------------
// Flash attention, triangle-paired CTAs, K fragments register-resident.
// ---------------------------------------------------------------------------
#define KOFF(t, l)  ((t) * 4608 + (l) * 2304)
#define QOFF(bf, l) (9216 + (bf) * 4608 + (l) * 2304)
#define VOFF(bf, l) (18432 + (bf) * 4608 + (l) * 2304)
#define ATTN_SMEM_U32 27904   // 111616 B

__device__ __forceinline__ void online_update(
    float (&sacc)[4][4], float& m_lo, float& m_hi, float& l_lo, float& l_hi,
    float (&o)[8][4], u32 (&pah)[2][4], u32 (&pal)[2][4])
{
    float mx0 = -INFINITY, mx1 = -INFINITY;
    #pragma unroll
    for (int nt = 0; nt < 4; nt++) {
        mx0 = fmaxf(mx0, fmaxf(sacc[nt][0], sacc[nt][1]));
        mx1 = fmaxf(mx1, fmaxf(sacc[nt][2], sacc[nt][3]));
    }
    mx0 = fmaxf(mx0, __shfl_xor_sync(0xffffffffu, mx0, 1));
    mx0 = fmaxf(mx0, __shfl_xor_sync(0xffffffffu, mx0, 2));
    mx1 = fmaxf(mx1, __shfl_xor_sync(0xffffffffu, mx1, 1));
    mx1 = fmaxf(mx1, __shfl_xor_sync(0xffffffffu, mx1, 2));
    float mn0 = fmaxf(m_lo, mx0), mn1 = fmaxf(m_hi, mx1);
    float sum0 = 0.f, sum1 = 0.f;
    #pragma unroll
    for (int nt = 0; nt < 4; nt++) {
        sacc[nt][0] = __expf(fmaxf(sacc[nt][0] - mn0, -88.f));
        sacc[nt][1] = __expf(fmaxf(sacc[nt][1] - mn0, -88.f));
        sacc[nt][2] = __expf(fmaxf(sacc[nt][2] - mn1, -88.f));
        sacc[nt][3] = __expf(fmaxf(sacc[nt][3] - mn1, -88.f));
        sum0 += sacc[nt][0] + sacc[nt][1];
        sum1 += sacc[nt][2] + sacc[nt][3];
    }
    sum0 += __shfl_xor_sync(0xffffffffu, sum0, 1);
    sum0 += __shfl_xor_sync(0xffffffffu, sum0, 2);
    sum1 += __shfl_xor_sync(0xffffffffu, sum1, 1);
    sum1 += __shfl_xor_sync(0xffffffffu, sum1, 2);
    float cf0 = __expf(fmaxf(m_lo - mn0, -88.f));
    float cf1 = __expf(fmaxf(m_hi - mn1, -88.f));
    l_lo = l_lo * cf0 + sum0; l_hi = l_hi * cf1 + sum1;
    m_lo = mn0; m_hi = mn1;
    #pragma unroll
    for (int nt = 0; nt < 8; nt++) {
        o[nt][0] *= cf0; o[nt][1] *= cf0;
        o[nt][2] *= cf1; o[nt][3] *= cf1;
    }
    #pragma unroll
    for (int kp = 0; kp < 2; kp++) {
        float p00 = sacc[2*kp][0],   p01 = sacc[2*kp][1];
        float p02 = sacc[2*kp][2],   p03 = sacc[2*kp][3];
        float p10 = sacc[2*kp+1][0], p11 = sacc[2*kp+1][1];
        float p12 = sacc[2*kp+1][2], p13 = sacc[2*kp+1][3];
        float h00 = bfh(p00), h01 = bfh(p01), h02 = bfh(p02), h03 = bfh(p03);
        float h10 = bfh(p10), h11 = bfh(p11), h12 = bfh(p12), h13 = bfh(p13);
        pah[kp][0] = pkbf(h00, h01);
        pah[kp][1] = pkbf(h02, h03);
        pah[kp][2] = pkbf(h10, h11);
        pah[kp][3] = pkbf(h12, h13);
        pal[kp][0] = pkbf(p00 - h00, p01 - h01);
        pal[kp][1] = pkbf(p02 - h02, p03 - h03);
        pal[kp][2] = pkbf(p10 - h10, p11 - h11);
        pal[kp][3] = pkbf(p12 - h12, p13 - h13);
    }
}

__device__ __forceinline__ void merge_write(
    float (&o)[8][4], float m_lo, float m_hi, float l_lo, float l_hi,
    float* mlbuf, float* obuf, int slab, int half, int rr, int q,
    float* __restrict__ out, int b, int t0)
{
    __syncthreads();
    if (q == 0) {
        int base = (slab * 2 + half) * 16;
        mlbuf[(base + rr) * 2]         = m_lo;
        mlbuf[(base + rr) * 2 + 1]     = l_lo;
        mlbuf[(base + rr + 8) * 2]     = m_hi;
        mlbuf[(base + rr + 8) * 2 + 1] = l_hi;
    }
    __syncthreads();
    int ob = (slab * 2 + (1 - half)) * 16;
    float mo0 = mlbuf[(ob + rr) * 2],     lo0 = mlbuf[(ob + rr) * 2 + 1];
    float mo1 = mlbuf[(ob + rr + 8) * 2], lo1 = mlbuf[(ob + rr + 8) * 2 + 1];
    float M0 = fmaxf(m_lo, mo0), M1 = fmaxf(m_hi, mo1);
    float f0 = __expf(fmaxf(m_lo - M0, -88.f));
    float f1 = __expf(fmaxf(m_hi - M1, -88.f));
    float g0 = __expf(fmaxf(mo0 - M0, -88.f));
    float g1 = __expf(fmaxf(mo1 - M1, -88.f));
    float L0 = l_lo * f0 + lo0 * g0;
    float L1 = l_hi * f1 + lo1 * g1;
    #pragma unroll
    for (int nt = 0; nt < 8; nt++) {
        o[nt][0] *= f0; o[nt][1] *= f0;
        o[nt][2] *= f1; o[nt][3] *= f1;
    }
    if (half == 1) {
        #pragma unroll
        for (int nt = 0; nt < 8; nt++) {
            int cb = nt * 8 + 2 * q;
            obuf[(slab * 16 + rr) * 64 + cb]         = o[nt][0];
            obuf[(slab * 16 + rr) * 64 + cb + 1]     = o[nt][1];
            obuf[(slab * 16 + rr + 8) * 64 + cb]     = o[nt][2];
            obuf[(slab * 16 + rr + 8) * 64 + cb + 1] = o[nt][3];
        }
    }
    __syncthreads();
    if (half == 0) {
        float i0 = 1.f / L0, i1 = 1.f / L1;
        size_t rb = ((size_t)b * TT + t0 + slab * 16 + rr) * 64;
        #pragma unroll
        for (int nt = 0; nt < 8; nt++) {
            int cb = nt * 8 + 2 * q;
            float2 r1;
            r1.x = (o[nt][0] + obuf[(slab * 16 + rr) * 64 + cb]) * i0;
            r1.y = (o[nt][1] + obuf[(slab * 16 + rr) * 64 + cb + 1]) * i0;
            *(float2*)(out + rb + cb) = r1;
            float2 r2;
            r2.x = (o[nt][2] + obuf[(slab * 16 + rr + 8) * 64 + cb]) * i1;
            r2.y = (o[nt][3] + obuf[(slab * 16 + rr + 8) * 64 + cb + 1]) * i1;
            *(float2*)(out + rb + 8 * 64 + cb) = r2;
        }
    }
}

__global__ __launch_bounds__(256) void attn_kernel(float* __restrict__ out)
{
    extern __shared__ u32 sm[];
    float* mlbuf = (float*)(sm + 27648);
    float* obuf  = (float*)(sm + 9216);

    const int tid  = threadIdx.x;
    const int wid  = tid >> 5, lane = tid & 31;
    const int slab = wid >> 1, half = wid & 1;
    const int rr   = lane >> 2, q = lane & 3;
    const int b    = blockIdx.y;
    const int bx   = blockIdx.x;          // tile A = bx, tile B = 31-bx
    const int tB   = 31 - bx;
    const int last = tB;

    const u32 sb = smem_u32(sm);
    const int lane7 = lane & 7;
    const int arow  = lane7 + (lane & 8);
    const int acx4  = (lane & 16) ? 16 : 0;
    const int bex4  = (lane & 8) ? 16 : 0;

    // stage K (both tiles) + Q/V(st=0)
    stage64(sb + (u32)KOFF(0,0) * 4, g_kh + ((size_t)b * TT + bx * 64) * 32, 32, tid);
    stage64(sb + (u32)KOFF(0,1) * 4, g_kl + ((size_t)b * TT + bx * 64) * 32, 32, tid);
    stage64(sb + (u32)KOFF(1,0) * 4, g_kh + ((size_t)b * TT + tB * 64) * 32, 32, tid);
    stage64(sb + (u32)KOFF(1,1) * 4, g_kl + ((size_t)b * TT + tB * 64) * 32, 32, tid);
    stage64(sb + (u32)QOFF(0,0) * 4, g_qh + (size_t)b * TT * 32, 32, tid);
    stage64(sb + (u32)QOFF(0,1) * 4, g_ql + (size_t)b * TT * 32, 32, tid);
    stage64(sb + (u32)VOFF(0,0) * 4, g_vth + (size_t)b * 65536, 1024, tid);
    stage64(sb + (u32)VOFF(0,1) * 4, g_vtl + (size_t)b * 65536, 1024, tid);
    cp_commit();
    cp_wait0();
    __syncthreads();

    // hoist K fragments to registers: [tile][hl][kt][4]
    u32 kf[2][2][4][4];
    #pragma unroll
    for (int t = 0; t < 2; t++)
        #pragma unroll
        for (int l = 0; l < 2; l++) {
            u32 base = sb + (u32)(KOFF(t,l) + (slab * 16 + arow) * PST) * 4 + acx4;
            #pragma unroll
            for (int kt = 0; kt < 4; kt++)
                ldm_x4(kf[t][l][kt], base + kt * 32);
        }

    float oA[8][4], oB[8][4];
    #pragma unroll
    for (int i = 0; i < 8; i++)
        #pragma unroll
        for (int j = 0; j < 4; j++) { oA[i][j] = 0.f; oB[i][j] = 0.f; }
    float mA0 = -INFINITY, mA1 = -INFINITY, lA0 = 0.f, lA1 = 0.f;
    float mB0 = -INFINITY, mB1 = -INFINITY, lB0 = 0.f, lB1 = 0.f;

    for (int st = 0; st <= last; st++) {
        const int buf = st & 1;
        if (st > 0) { cp_wait0(); __syncthreads(); }
        if (st < last) {
            int nb = buf ^ 1, s1 = st + 1;
            stage64(sb + (u32)QOFF(nb,0) * 4, g_qh + ((size_t)b * TT + s1 * 64) * 32, 32, tid);
            stage64(sb + (u32)QOFF(nb,1) * 4, g_ql + ((size_t)b * TT + s1 * 64) * 32, 32, tid);
            stage64(sb + (u32)VOFF(nb,0) * 4, g_vth + (size_t)b * 65536 + s1 * 32, 1024, tid);
            stage64(sb + (u32)VOFF(nb,1) * 4, g_vtl + (size_t)b * 65536 + s1 * 32, 1024, tid);
            cp_commit();
        }
        const bool actA = (st <= bx);
        const u32 qB  = sb + (u32)(QOFF(buf,0) + (half * 32 + lane7) * PST) * 4 + bex4;
        const u32 qBl = qB + 2304 * 4;
        const u32 vB  = sb + (u32)(VOFF(buf,0) + lane7 * PST + half * 16) * 4 + bex4;
        const u32 vBl = vB + 2304 * 4;

        // ---- S for both tiles (K from registers) ----
        float sA[4][4], sB4[4][4];
        #pragma unroll
        for (int i = 0; i < 4; i++)
            #pragma unroll
            for (int j = 0; j < 4; j++) { sA[i][j] = 0.f; sB4[i][j] = 0.f; }
        #pragma unroll
        for (int kt = 0; kt < 4; kt++) {
            #pragma unroll
            for (int nt = 0; nt < 4; nt++) {
                u32 bh[2], bl[2];
                ldm_x2(bh, qB  + nt * (8 * PST * 4) + kt * 32);
                ldm_x2(bl, qBl + nt * (8 * PST * 4) + kt * 32);
                if (actA) {
                    mma16816(sA[nt], kf[0][0][kt], bh);
                    mma16816(sA[nt], kf[0][0][kt], bl);
                    mma16816(sA[nt], kf[0][1][kt], bh);
                }
                mma16816(sB4[nt], kf[1][0][kt], bh);
                mma16816(sB4[nt], kf[1][0][kt], bl);
                mma16816(sB4[nt], kf[1][1][kt], bh);
            }
        }

        const int s0 = st * 64;
        u32 pahA[2][4], palA[2][4], pahB[2][4], palB[2][4];
        if (actA) {
            if (st == bx) {
                int tlo = bx * 64 + slab * 16 + rr, thi = tlo + 8;
                #pragma unroll
                for (int nt = 0; nt < 4; nt++) {
                    int sc = s0 + half * 32 + nt * 8 + 2 * q;
                    if (sc > tlo)     sA[nt][0] = -INFINITY;
                    if (sc + 1 > tlo) sA[nt][1] = -INFINITY;
                    if (sc > thi)     sA[nt][2] = -INFINITY;
                    if (sc + 1 > thi) sA[nt][3] = -INFINITY;
                }
            }
            online_update(sA, mA0, mA1, lA0, lA1, oA, pahA, palA);
        }
        if (st == tB) {
            int tlo = tB * 64 + slab * 16 + rr, thi = tlo + 8;
            #pragma unroll
            for (int nt = 0; nt < 4; nt++) {
                int sc = s0 + half * 32 + nt * 8 + 2 * q;
                if (sc > tlo)     sB4[nt][0] = -INFINITY;
                if (sc + 1 > tlo) sB4[nt][1] = -INFINITY;
                if (sc > thi)     sB4[nt][2] = -INFINITY;
                if (sc + 1 > thi) sB4[nt][3] = -INFINITY;
            }
        }
        online_update(sB4, mB0, mB1, lB0, lB1, oB, pahB, palB);

        // ---- O += P.V (V fragments shared between tiles) ----
        #pragma unroll
        for (int kp = 0; kp < 2; kp++) {
            #pragma unroll
            for (int nt = 0; nt < 8; nt++) {
                u32 vh2[2], vl2[2];
                ldm_x2(vh2, vB  + nt * (8 * PST * 4) + kp * 32);
                ldm_x2(vl2, vBl + nt * (8 * PST * 4) + kp * 32);
                if (actA) {
                    mma16816(oA[nt], pahA[kp], vh2);
                    mma16816(oA[nt], pahA[kp], vl2);
                    mma16816(oA[nt], palA[kp], vh2);
                }
                mma16816(oB[nt], pahB[kp], vh2);
                mma16816(oB[nt], pahB[kp], vl2);
                mma16816(oB[nt], palB[kp], vh2);
            }
        }
    }

    merge_write(oA, mA0, mA1, lA0, lA1, mlbuf, obuf, slab, half, rr, q, out, b, bx * 64);
    merge_write(oB, mB0, mB1, lB0, lB1, mlbuf, obuf, slab, half, rr, q, out, b, tB * 64);
}

// ---------------------------------------------------------------------------
extern "C" void kernel_launch(void* const* d_in, const int* in_sizes, int n_in,
                              void* d_out, int out_size)
{
    const float* x  = (const float*)d_in[0];
    const float* Wq = (const float*)d_in[1];
    const float* Wk = (const float*)d_in[2];
    const float* Wv = (const float*)d_in[3];
    float* out = (float*)d_out;

    prep_w_kernel<<<384, 256>>>(Wq, Wk, Wv);
    prep_x_kernel<<<8192, 256>>>(x);

    cudaFuncSetAttribute(proj_kernel,
                         cudaFuncAttributeMaxDynamicSharedMemorySize,
                         PROJ_SMEM_U32 * 4);
    proj_kernel<<<BT / 64, 256, PROJ_SMEM_U32 * 4>>>();

    vt_kernel<<<1024, 256>>>();

    cudaFuncSetAttribute(attn_kernel,
                         cudaFuncAttributeMaxDynamicSharedMemorySize,
                         ATTN_SMEM_U32 * 4);
    dim3 grid(16, BB);
    attn_kernel<<<grid, 256, ATTN_SMEM_U32 * 4>>>(out);
}

// round 10
// speedup vs baseline: 1.1475x; 1.1475x over previous
#include <cuda_runtime.h>
#include <cuda_bf16.h>
#include <math.h>

#define BB   8
#define TT   2048
#define DIN  1024
#define HH   64
#define BT   (BB*TT)
#define PST  36      // smem row stride in u32 (144B) -> conflict-free ldmatrix

typedef unsigned int u32;

// Packed bf16x2 hi/lo scratch (q,k,v) and prepped weights.
__device__ __align__(16) u32 g_qh[BT*32];
__device__ __align__(16) u32 g_ql[BT*32];
__device__ __align__(16) u32 g_kh[BT*32];
__device__ __align__(16) u32 g_kl[BT*32];
__device__ __align__(16) u32 g_vh[BT*32];
__device__ __align__(16) u32 g_vl[BT*32];
// V transposed for attention: [b][h 0..63][sp 0..1023]
__device__ __align__(16) u32 g_vth[BB*64*1024];
__device__ __align__(16) u32 g_vtl[BB*64*1024];
// W fragment-ready: [n 0..191][kk 0..511] u32 = pack(W[2kk][n], W[2kk+1][n])
__device__ __align__(16) u32 g_wh[192*512];
__device__ __align__(16) u32 g_wl[192*512];

// ---- helpers ---------------------------------------------------------------
__device__ __forceinline__ u32 pkbf(float lo, float hi) {
    u32 r; asm("cvt.rn.bf16x2.f32 %0, %1, %2;" : "=r"(r) : "f"(hi), "f"(lo));
    return r;
}
__device__ __forceinline__ float bfh(float x) {
    return __bfloat162float(__float2bfloat16(x));
}
__device__ __forceinline__ void mma16816(float* c, const u32* a, const u32* b) {
    asm volatile(
        "mma.sync.aligned.m16n8k16.row.col.f32.bf16.bf16.f32 "
        "{%0,%1,%2,%3}, {%4,%5,%6,%7}, {%8,%9}, {%0,%1,%2,%3};"
        : "+f"(c[0]), "+f"(c[1]), "+f"(c[2]), "+f"(c[3])
        : "r"(a[0]), "r"(a[1]), "r"(a[2]), "r"(a[3]), "r"(b[0]), "r"(b[1]));
}
__device__ __forceinline__ void ldm_x4(u32* r, u32 addr) {
    asm volatile("ldmatrix.sync.aligned.m8n8.x4.shared.b16 {%0,%1,%2,%3}, [%4];"
        : "=r"(r[0]), "=r"(r[1]), "=r"(r[2]), "=r"(r[3]) : "r"(addr));
}
__device__ __forceinline__ void ldm_x2(u32* r, u32 addr) {
    asm volatile("ldmatrix.sync.aligned.m8n8.x2.shared.b16 {%0,%1}, [%2];"
        : "=r"(r[0]), "=r"(r[1]) : "r"(addr));
}
__device__ __forceinline__ void cp16(u32 smem, const void* g) {
    asm volatile("cp.async.cg.shared.global [%0], [%1], 16;" :: "r"(smem), "l"(g));
}
__device__ __forceinline__ void cp_commit() {
    asm volatile("cp.async.commit_group;" ::: "memory");
}
__device__ __forceinline__ void cp_wait0() {
    asm volatile("cp.async.wait_group 0;" ::: "memory");
}
__device__ __forceinline__ u32 smem_u32(const void* p) {
    u32 a;
    asm("{ .reg .u64 t; cvta.to.shared.u64 t, %1; cvt.u32.u64 %0, t; }"
        : "=r"(a) : "l"(p));
    return a;
}

// ---------------------------------------------------------------------------
// Prep: W -> bf16 hi/lo packed, fragment-ready.
// ---------------------------------------------------------------------------
__global__ __launch_bounds__(256) void prep_w_kernel(
    const float* __restrict__ Wq, const float* __restrict__ Wk,
    const float* __restrict__ Wv)
{
    int idx = blockIdx.x * 256 + threadIdx.x;
    int n = idx % 192, kk = idx / 192;
    const float* W = (n < 64) ? Wq : ((n < 128) ? Wk : Wv);
    int col = n & 63;
    float w0 = W[(size_t)(2 * kk) * HH + col];
    float w1 = W[(size_t)(2 * kk + 1) * HH + col];
    float h0 = bfh(w0), h1 = bfh(w1);
    g_wh[n * 512 + kk] = pkbf(h0, h1);
    g_wl[n * 512 + kk] = pkbf(w0 - h0, w1 - h1);
}

// ---------------------------------------------------------------------------
// Staging helpers (cp.async, 16B chunks).
// ---------------------------------------------------------------------------
__device__ __forceinline__ void stage64(u32 sbyte, const u32* g, int gstride, int tid) {
    #pragma unroll
    for (int u = 0; u < 2; u++) {
        int idx = tid + u * 256;      // 512 16B chunks
        int row = idx >> 3, ch = idx & 7;
        cp16(sbyte + (u32)(row * PST + ch * 4) * 4, g + (size_t)row * gstride + ch * 4);
    }
}
__device__ __forceinline__ void stage192(u32 sbyte, const u32* g, int tid) {
    #pragma unroll
    for (int u = 0; u < 6; u++) {
        int idx = tid + u * 256;      // 1536 16B chunks
        int row = idx >> 3, ch = idx & 7;
        cp16(sbyte + (u32)(row * PST + ch * 4) * 4, g + (size_t)row * 512 + ch * 4);
    }
}
// raw X: 64 rows x 64 fp32, smem row stride 68 floats
__device__ __forceinline__ void stageXraw(u32 sbyte, const float* g, int tid) {
    #pragma unroll
    for (int u = 0; u < 4; u++) {
        int idx = tid + u * 256;      // 1024 16B chunks
        int row = idx >> 4, ch = idx & 15;
        cp16(sbyte + (u32)(row * 68 + ch * 4) * 4, g + (size_t)row * DIN + ch * 4);
    }
}

// ---------------------------------------------------------------------------
// Fused QKV projection: cp.async double-buffered (raw X + packed W),
// in-smem X conversion, ldmatrix + bf16x3 mma.
// smem (u32): XRAW0 0 | XRAW1 4352 | XH 8704 | XL 11008 | W0 13312 | W1 27136
// ---------------------------------------------------------------------------
#define XRAW0 0
#define XRAW1 4352
#define PXH   8704
#define PXL   11008
#define PW0   13312
#define PW1   27136
#define PROJ_SMEM_U32 40960   // 163840 B

__global__ __launch_bounds__(256) void proj_kernel(const float* __restrict__ x)
{
    extern __shared__ u32 sm[];
    const u32 sbx = smem_u32(sm);
    const int tid  = threadIdx.x;
    const int wid  = tid >> 5, lane = tid & 31;
    const int slab = wid >> 1, half = wid & 1;
    const int rr   = lane >> 2, q = lane & 3;
    const int m0   = blockIdx.x * 64;

    const int lane7 = lane & 7;
    const int arow  = lane7 + (lane & 8);
    const int acx4  = (lane & 16) ? 16 : 0;
    const int bex4  = (lane & 8) ? 16 : 0;
    const u32 aH = sbx + (u32)(PXH + (slab * 16 + arow) * PST) * 4 + acx4;
    const u32 aL = aH + 2304 * 4;

    // preload chunk 0
    stageXraw(sbx + XRAW0 * 4, x + (size_t)m0 * DIN, tid);
    stage192(sbx + PW0 * 4,          g_wh, tid);
    stage192(sbx + (PW0 + 6912) * 4, g_wl, tid);
    cp_commit();

    float acc[12][4];
    #pragma unroll
    for (int i = 0; i < 12; i++)
        #pragma unroll
        for (int j = 0; j < 4; j++) acc[i][j] = 0.f;

    for (int c = 0; c < 16; c++) {
        const int buf = c & 1;
        cp_wait0();
        __syncthreads();
        if (c < 15) {
            const int kk = (c + 1) * 32;
            const u32 xr = (buf ? XRAW0 : XRAW1);
            const u32 wb = (buf ? PW0 : PW1);
            stageXraw(sbx + xr * 4, x + (size_t)m0 * DIN + (c + 1) * 64, tid);
            stage192(sbx + wb * 4,          g_wh + kk, tid);
            stage192(sbx + (wb + 6912) * 4, g_wl + kk, tid);
            cp_commit();
        }
        // convert raw X (this buf) -> packed XH/XL
        {
            const float* xraw = (const float*)(sm + (buf ? XRAW1 : XRAW0));
            u32* sxh = sm + PXH;
            u32* sxl = sm + PXL;
            #pragma unroll
            for (int u = 0; u < 4; u++) {
                int idx = tid + u * 256;
                int row = idx >> 4, f4 = idx & 15;
                float4 v = *(const float4*)&xraw[row * 68 + 4 * f4];
                float h0 = bfh(v.x), h1 = bfh(v.y), h2 = bfh(v.z), h3 = bfh(v.w);
                sxh[row * PST + 2 * f4]     = pkbf(h0, h1);
                sxh[row * PST + 2 * f4 + 1] = pkbf(h2, h3);
                sxl[row * PST + 2 * f4]     = pkbf(v.x - h0, v.y - h1);
                sxl[row * PST + 2 * f4 + 1] = pkbf(v.z - h2, v.w - h3);
            }
        }
        __syncthreads();

        const u32 wb = (u32)(buf ? PW1 : PW0);
        const u32 bH = sbx + (wb + (half * 96 + lane7) * PST) * 4 + bex4;
        const u32 bL = bH + 6912 * 4;

        #pragma unroll
        for (int kt = 0; kt < 4; kt++) {
            u32 ah[4], al[4];
            ldm_x4(ah, aH + kt * 32);
            ldm_x4(al, aL + kt * 32);
            #pragma unroll
            for (int nt = 0; nt < 12; nt++) {
                u32 bh[2], bl[2];
                ldm_x2(bh, bH + nt * (8 * PST * 4) + kt * 32);
                ldm_x2(bl, bL + nt * (8 * PST * 4) + kt * 32);
                mma16816(acc[nt], ah, bh);
                mma16816(acc[nt], ah, bl);
                mma16816(acc[nt], al, bh);
            }
        }
    }

    // epilogue: split to bf16 hi/lo packed q/k/v; fold 0.125 into K
    u32* const GH[3] = {g_qh, g_kh, g_vh};
    u32* const GL[3] = {g_ql, g_kl, g_vl};
    const int row0 = m0 + slab * 16 + rr;
    #pragma unroll
    for (int nt = 0; nt < 12; nt++) {
        int colb = half * 96 + nt * 8;
        int mat = colb >> 6;
        int hqb = (colb & 63) >> 1;
        float s = (mat == 1) ? 0.125f : 1.f;
        float a0 = acc[nt][0] * s, a1 = acc[nt][1] * s;
        float a2 = acc[nt][2] * s, a3 = acc[nt][3] * s;
        float h0 = bfh(a0), h1 = bfh(a1), h2 = bfh(a2), h3 = bfh(a3);
        GH[mat][(size_t)row0 * 32 + hqb + q]       = pkbf(h0, h1);
        GL[mat][(size_t)row0 * 32 + hqb + q]       = pkbf(a0 - h0, a1 - h1);
        GH[mat][(size_t)(row0 + 8) * 32 + hqb + q] = pkbf(h2, h3);
        GL[mat][(size_t)(row0 + 8) * 32 + hqb + q] = pkbf(a2 - h2, a3 - h3);
    }
}

// ---------------------------------------------------------------------------
// V transpose: g_vh/g_vl -> g_vth/g_vtl ([b][h][s-pair]).
// ---------------------------------------------------------------------------
__global__ __launch_bounds__(256) void vt_kernel()
{
    int idx = blockIdx.x * 256 + threadIdx.x;
    int b  = idx >> 15;
    int r  = idx & 32767;
    int hq = r >> 10;
    int sp = r & 1023;
    const u32* vh = g_vh + (size_t)b * TT * 32;
    const u32* vl = g_vl + (size_t)b * TT * 32;
    u32 a = vh[(size_t)(2 * sp) * 32 + hq];
    u32 c = vh[(size_t)(2 * sp + 1) * 32 + hq];
    size_t ob = ((size_t)b * 64 + 2 * hq) * 1024 + sp;
    g_vth[ob]        = __byte_perm(a, c, 0x5410);
    g_vth[ob + 1024] = __byte_perm(a, c, 0x7632);
    a = vl[(size_t)(2 * sp) * 32 + hq];
    c = vl[(size_t)(2 * sp + 1) * 32 + hq];
    g_vtl[ob]        = __byte_perm(a, c, 0x5410);
    g_vtl[ob + 1024] = __byte_perm(a, c, 0x7632);
}

// ---------------------------------------------------------------------------
// Flash attention, triangle-paired CTAs, K fragments register-resident.
// ---------------------------------------------------------------------------
#define KOFF(t, l)  ((t) * 4608 + (l) * 2304)
#define QOFF(bf, l) (9216 + (bf) * 4608 + (l) * 2304)
#define VOFF(bf, l) (18432 + (bf) * 4608 + (l) * 2304)
#define ATTN_SMEM_U32 27904   // 111616 B

__device__ __forceinline__ void online_update(
    float (&sacc)[4][4], float& m_lo, float& m_hi, float& l_lo, float& l_hi,
    float (&o)[8][4], u32 (&pah)[2][4], u32 (&pal)[2][4])
{
    float mx0 = -INFINITY, mx1 = -INFINITY;
    #pragma unroll
    for (int nt = 0; nt < 4; nt++) {
        mx0 = fmaxf(mx0, fmaxf(sacc[nt][0], sacc[nt][1]));
        mx1 = fmaxf(mx1, fmaxf(sacc[nt][2], sacc[nt][3]));
    }
    mx0 = fmaxf(mx0, __shfl_xor_sync(0xffffffffu, mx0, 1));
    mx0 = fmaxf(mx0, __shfl_xor_sync(0xffffffffu, mx0, 2));
    mx1 = fmaxf(mx1, __shfl_xor_sync(0xffffffffu, mx1, 1));
    mx1 = fmaxf(mx1, __shfl_xor_sync(0xffffffffu, mx1, 2));
    float mn0 = fmaxf(m_lo, mx0), mn1 = fmaxf(m_hi, mx1);
    float sum0 = 0.f, sum1 = 0.f;
    #pragma unroll
    for (int nt = 0; nt < 4; nt++) {
        sacc[nt][0] = __expf(fmaxf(sacc[nt][0] - mn0, -88.f));
        sacc[nt][1] = __expf(fmaxf(sacc[nt][1] - mn0, -88.f));
        sacc[nt][2] = __expf(fmaxf(sacc[nt][2] - mn1, -88.f));
        sacc[nt][3] = __expf(fmaxf(sacc[nt][3] - mn1, -88.f));
        sum0 += sacc[nt][0] + sacc[nt][1];
        sum1 += sacc[nt][2] + sacc[nt][3];
    }
    sum0 += __shfl_xor_sync(0xffffffffu, sum0, 1);
    sum0 += __shfl_xor_sync(0xffffffffu, sum0, 2);
    sum1 += __shfl_xor_sync(0xffffffffu, sum1, 1);
    sum1 += __shfl_xor_sync(0xffffffffu, sum1, 2);
    float cf0 = __expf(fmaxf(m_lo - mn0, -88.f));
    float cf1 = __expf(fmaxf(m_hi - mn1, -88.f));
    l_lo = l_lo * cf0 + sum0; l_hi = l_hi * cf1 + sum1;
    m_lo = mn0; m_hi = mn1;
    #pragma unroll
    for (int nt = 0; nt < 8; nt++) {
        o[nt][0] *= cf0; o[nt][1] *= cf0;
        o[nt][2] *= cf1; o[nt][3] *= cf1;
    }
    #pragma unroll
    for (int kp = 0; kp < 2; kp++) {
        float p00 = sacc[2*kp][0],   p01 = sacc[2*kp][1];
        float p02 = sacc[2*kp][2],   p03 = sacc[2*kp][3];
        float p10 = sacc[2*kp+1][0], p11 = sacc[2*kp+1][1];
        float p12 = sacc[2*kp+1][2], p13 = sacc[2*kp+1][3];
        float h00 = bfh(p00), h01 = bfh(p01), h02 = bfh(p02), h03 = bfh(p03);
        float h10 = bfh(p10), h11 = bfh(p11), h12 = bfh(p12), h13 = bfh(p13);
        pah[kp][0] = pkbf(h00, h01);
        pah[kp][1] = pkbf(h02, h03);
        pah[kp][2] = pkbf(h10, h11);
        pah[kp][3] = pkbf(h12, h13);
        pal[kp][0] = pkbf(p00 - h00, p01 - h01);
        pal[kp][1] = pkbf(p02 - h02, p03 - h03);
        pal[kp][2] = pkbf(p10 - h10, p11 - h11);
        pal[kp][3] = pkbf(p12 - h12, p13 - h13);
    }
}

__device__ __forceinline__ void merge_write(
    float (&o)[8][4], float m_lo, float m_hi, float l_lo, float l_hi,
    float* mlbuf, float* obuf, int slab, int half, int rr, int q,
    float* __restrict__ out, int b, int t0)
{
    __syncthreads();
    if (q == 0) {
        int base = (slab * 2 + half) * 16;
        mlbuf[(base + rr) * 2]         = m_lo;
        mlbuf[(base + rr) * 2 + 1]     = l_lo;
        mlbuf[(base + rr + 8) * 2]     = m_hi;
        mlbuf[(base + rr + 8) * 2 + 1] = l_hi;
    }
    __syncthreads();
    int ob = (slab * 2 + (1 - half)) * 16;
    float mo0 = mlbuf[(ob + rr) * 2],     lo0 = mlbuf[(ob + rr) * 2 + 1];
    float mo1 = mlbuf[(ob + rr + 8) * 2], lo1 = mlbuf[(ob + rr + 8) * 2 + 1];
    float M0 = fmaxf(m_lo, mo0), M1 = fmaxf(m_hi, mo1);
    float f0 = __expf(fmaxf(m_lo - M0, -88.f));
    float f1 = __expf(fmaxf(m_hi - M1, -88.f));
    float g0 = __expf(fmaxf(mo0 - M0, -88.f));
    float g1 = __expf(fmaxf(mo1 - M1, -88.f));
    float L0 = l_lo * f0 + lo0 * g0;
    float L1 = l_hi * f1 + lo1 * g1;
    #pragma unroll
    for (int nt = 0; nt < 8; nt++) {
        o[nt][0] *= f0; o[nt][1] *= f0;
        o[nt][2] *= f1; o[nt][3] *= f1;
    }
    if (half == 1) {
        #pragma unroll
        for (int nt = 0; nt < 8; nt++) {
            int cb = nt * 8 + 2 * q;
            obuf[(slab * 16 + rr) * 64 + cb]         = o[nt][0];
            obuf[(slab * 16 + rr) * 64 + cb + 1]     = o[nt][1];
            obuf[(slab * 16 + rr + 8) * 64 + cb]     = o[nt][2];
            obuf[(slab * 16 + rr + 8) * 64 + cb + 1] = o[nt][3];
        }
    }
    __syncthreads();
    if (half == 0) {
        float i0 = 1.f / L0, i1 = 1.f / L1;
        size_t rb = ((size_t)b * TT + t0 + slab * 16 + rr) * 64;
        #pragma unroll
        for (int nt = 0; nt < 8; nt++) {
            int cb = nt * 8 + 2 * q;
            float2 r1;
            r1.x = (o[nt][0] + obuf[(slab * 16 + rr) * 64 + cb]) * i0;
            r1.y = (o[nt][1] + obuf[(slab * 16 + rr) * 64 + cb + 1]) * i0;
            *(float2*)(out + rb + cb) = r1;
            float2 r2;
            r2.x = (o[nt][2] + obuf[(slab * 16 + rr + 8) * 64 + cb]) * i1;
            r2.y = (o[nt][3] + obuf[(slab * 16 + rr + 8) * 64 + cb + 1]) * i1;
            *(float2*)(out + rb + 8 * 64 + cb) = r2;
        }
    }
}

__global__ __launch_bounds__(256) void attn_kernel(float* __restrict__ out)
{
    extern __shared__ u32 sm[];
    float* mlbuf = (float*)(sm + 27648);
    float* obuf  = (float*)(sm + 9216);

    const int tid  = threadIdx.x;
    const int wid  = tid >> 5, lane = tid & 31;
    const int slab = wid >> 1, half = wid & 1;
    const int rr   = lane >> 2, q = lane & 3;
    const int b    = blockIdx.y;
    const int bx   = blockIdx.x;          // tile A = bx, tile B = 31-bx
    const int tB   = 31 - bx;
    const int last = tB;

    const u32 sb = smem_u32(sm);
    const int lane7 = lane & 7;
    const int arow  = lane7 + (lane & 8);
    const int acx4  = (lane & 16) ? 16 : 0;
    const int bex4  = (lane & 8) ? 16 : 0;

    // stage K (both tiles) + Q/V(st=0)
    stage64(sb + (u32)KOFF(0,0) * 4, g_kh + ((size_t)b * TT + bx * 64) * 32, 32, tid);
    stage64(sb + (u32)KOFF(0,1) * 4, g_kl + ((size_t)b * TT + bx * 64) * 32, 32, tid);
    stage64(sb + (u32)KOFF(1,0) * 4, g_kh + ((size_t)b * TT + tB * 64) * 32, 32, tid);
    stage64(sb + (u32)KOFF(1,1) * 4, g_kl + ((size_t)b * TT + tB * 64) * 32, 32, tid);
    stage64(sb + (u32)QOFF(0,0) * 4, g_qh + (size_t)b * TT * 32, 32, tid);
    stage64(sb + (u32)QOFF(0,1) * 4, g_ql + (size_t)b * TT * 32, 32, tid);
    stage64(sb + (u32)VOFF(0,0) * 4, g_vth + (size_t)b * 65536, 1024, tid);
    stage64(sb + (u32)VOFF(0,1) * 4, g_vtl + (size_t)b * 65536, 1024, tid);
    cp_commit();
    cp_wait0();
    __syncthreads();

    // hoist K fragments to registers: [tile][hl][kt][4]
    u32 kf[2][2][4][4];
    #pragma unroll
    for (int t = 0; t < 2; t++)
        #pragma unroll
        for (int l = 0; l < 2; l++) {
            u32 base = sb + (u32)(KOFF(t,l) + (slab * 16 + arow) * PST) * 4 + acx4;
            #pragma unroll
            for (int kt = 0; kt < 4; kt++)
                ldm_x4(kf[t][l][kt], base + kt * 32);
        }

    float oA[8][4], oB[8][4];
    #pragma unroll
    for (int i = 0; i < 8; i++)
        #pragma unroll
        for (int j = 0; j < 4; j++) { oA[i][j] = 0.f; oB[i][j] = 0.f; }
    float mA0 = -INFINITY, mA1 = -INFINITY, lA0 = 0.f, lA1 = 0.f;
    float mB0 = -INFINITY, mB1 = -INFINITY, lB0 = 0.f, lB1 = 0.f;

    for (int st = 0; st <= last; st++) {
        const int buf = st & 1;
        if (st > 0) { cp_wait0(); __syncthreads(); }
        if (st < last) {
            int nb = buf ^ 1, s1 = st + 1;
            stage64(sb + (u32)QOFF(nb,0) * 4, g_qh + ((size_t)b * TT + s1 * 64) * 32, 32, tid);
            stage64(sb + (u32)QOFF(nb,1) * 4, g_ql + ((size_t)b * TT + s1 * 64) * 32, 32, tid);
            stage64(sb + (u32)VOFF(nb,0) * 4, g_vth + (size_t)b * 65536 + s1 * 32, 1024, tid);
            stage64(sb + (u32)VOFF(nb,1) * 4, g_vtl + (size_t)b * 65536 + s1 * 32, 1024, tid);
            cp_commit();
        }
        const bool actA = (st <= bx);
        const u32 qB  = sb + (u32)(QOFF(buf,0) + (half * 32 + lane7) * PST) * 4 + bex4;
        const u32 qBl = qB + 2304 * 4;
        const u32 vB  = sb + (u32)(VOFF(buf,0) + lane7 * PST + half * 16) * 4 + bex4;
        const u32 vBl = vB + 2304 * 4;

        // ---- S for both tiles (K from registers) ----
        float sA[4][4], sB4[4][4];
        #pragma unroll
        for (int i = 0; i < 4; i++)
            #pragma unroll
            for (int j = 0; j < 4; j++) { sA[i][j] = 0.f; sB4[i][j] = 0.f; }
        #pragma unroll
        for (int kt = 0; kt < 4; kt++) {
            #pragma unroll
            for (int nt = 0; nt < 4; nt++) {
                u32 bh[2], bl[2];
                ldm_x2(bh, qB  + nt * (8 * PST * 4) + kt * 32);
                ldm_x2(bl, qBl + nt * (8 * PST * 4) + kt * 32);
                if (actA) {
                    mma16816(sA[nt], kf[0][0][kt], bh);
                    mma16816(sA[nt], kf[0][0][kt], bl);
                    mma16816(sA[nt], kf[0][1][kt], bh);
                }
                mma16816(sB4[nt], kf[1][0][kt], bh);
                mma16816(sB4[nt], kf[1][0][kt], bl);
                mma16816(sB4[nt], kf[1][1][kt], bh);
            }
        }

        const int s0 = st * 64;
        u32 pahA[2][4], palA[2][4], pahB[2][4], palB[2][4];
        if (actA) {
            if (st == bx) {
                int tlo = bx * 64 + slab * 16 + rr, thi = tlo + 8;
                #pragma unroll
                for (int nt = 0; nt < 4; nt++) {
                    int sc = s0 + half * 32 + nt * 8 + 2 * q;
                    if (sc > tlo)     sA[nt][0] = -INFINITY;
                    if (sc + 1 > tlo) sA[nt][1] = -INFINITY;
                    if (sc > thi)     sA[nt][2] = -INFINITY;
                    if (sc + 1 > thi) sA[nt][3] = -INFINITY;
                }
            }
            online_update(sA, mA0, mA1, lA0, lA1, oA, pahA, palA);
        }
        if (st == tB) {
            int tlo = tB * 64 + slab * 16 + rr, thi = tlo + 8;
            #pragma unroll
            for (int nt = 0; nt < 4; nt++) {
                int sc = s0 + half * 32 + nt * 8 + 2 * q;
                if (sc > tlo)     sB4[nt][0] = -INFINITY;
                if (sc + 1 > tlo) sB4[nt][1] = -INFINITY;
                if (sc > thi)     sB4[nt][2] = -INFINITY;
                if (sc + 1 > thi) sB4[nt][3] = -INFINITY;
            }
        }
        online_update(sB4, mB0, mB1, lB0, lB1, oB, pahB, palB);

        // ---- O += P.V (V fragments shared between tiles) ----
        #pragma unroll
        for (int kp = 0; kp < 2; kp++) {
            #pragma unroll
            for (int nt = 0; nt < 8; nt++) {
                u32 vh2[2], vl2[2];
                ldm_x2(vh2, vB  + nt * (8 * PST * 4) + kp * 32);
                ldm_x2(vl2, vBl + nt * (8 * PST * 4) + kp * 32);
                if (actA) {
                    mma16816(oA[nt], pahA[kp], vh2);
                    mma16816(oA[nt], pahA[kp], vl2);
                    mma16816(oA[nt], palA[kp], vh2);
                }
                mma16816(oB[nt], pahB[kp], vh2);
                mma16816(oB[nt], pahB[kp], vl2);
                mma16816(oB[nt], palB[kp], vh2);
            }
        }
    }

    merge_write(oA, mA0, mA1, lA0, lA1, mlbuf, obuf, slab, half, rr, q, out, b, bx * 64);
    merge_write(oB, mB0, mB1, lB0, lB1, mlbuf, obuf, slab, half, rr, q, out, b, tB * 64);
}

// ---------------------------------------------------------------------------
extern "C" void kernel_launch(void* const* d_in, const int* in_sizes, int n_in,
                              void* d_out, int out_size)
{
    const float* x  = (const float*)d_in[0];
    const float* Wq = (const float*)d_in[1];
    const float* Wk = (const float*)d_in[2];
    const float* Wv = (const float*)d_in[3];
    float* out = (float*)d_out;

    prep_w_kernel<<<384, 256>>>(Wq, Wk, Wv);

    cudaFuncSetAttribute(proj_kernel,
                         cudaFuncAttributeMaxDynamicSharedMemorySize,
                         PROJ_SMEM_U32 * 4);
    proj_kernel<<<BT / 64, 256, PROJ_SMEM_U32 * 4>>>(x);

    vt_kernel<<<1024, 256>>>();

    cudaFuncSetAttribute(attn_kernel,
                         cudaFuncAttributeMaxDynamicSharedMemorySize,
                         ATTN_SMEM_U32 * 4);
    dim3 grid(16, BB);
    attn_kernel<<<grid, 256, ATTN_SMEM_U32 * 4>>>(out);
}

// round 11
// speedup vs baseline: 1.2289x; 1.0710x over previous
#include <cuda_runtime.h>
#include <cuda_bf16.h>
#include <math.h>

#define BB   8
#define TT   2048
#define DIN  1024
#define HH   64
#define BT   (BB*TT)
#define PST  36      // attn smem row stride in u32 (144B) -> conflict-free ldmatrix

typedef unsigned int u32;

// Packed bf16x2 hi/lo scratch (q,k) and transposed v, prepped weights.
__device__ __align__(16) u32 g_qh[BT*32];
__device__ __align__(16) u32 g_ql[BT*32];
__device__ __align__(16) u32 g_kh[BT*32];
__device__ __align__(16) u32 g_kl[BT*32];
// V transposed: [b][h 0..63][sp 0..1023], u32 = pack(v[2sp][h], v[2sp+1][h])
__device__ __align__(16) u32 g_vth[BB*64*1024];
__device__ __align__(16) u32 g_vtl[BB*64*1024];
// W fragment-ready: [n 0..191][kk 0..511] u32 = pack(W[2kk][n], W[2kk+1][n])
__device__ __align__(16) u32 g_wh[192*512];
__device__ __align__(16) u32 g_wl[192*512];

// ---- helpers ---------------------------------------------------------------
__device__ __forceinline__ u32 pkbf(float lo, float hi) {
    u32 r; asm("cvt.rn.bf16x2.f32 %0, %1, %2;" : "=r"(r) : "f"(hi), "f"(lo));
    return r;
}
__device__ __forceinline__ float bfh(float x) {
    return __bfloat162float(__float2bfloat16(x));
}
__device__ __forceinline__ void mma16816(float* c, const u32* a, const u32* b) {
    asm volatile(
        "mma.sync.aligned.m16n8k16.row.col.f32.bf16.bf16.f32 "
        "{%0,%1,%2,%3}, {%4,%5,%6,%7}, {%8,%9}, {%0,%1,%2,%3};"
        : "+f"(c[0]), "+f"(c[1]), "+f"(c[2]), "+f"(c[3])
        : "r"(a[0]), "r"(a[1]), "r"(a[2]), "r"(a[3]), "r"(b[0]), "r"(b[1]));
}
__device__ __forceinline__ void ldm_x4(u32* r, u32 addr) {
    asm volatile("ldmatrix.sync.aligned.m8n8.x4.shared.b16 {%0,%1,%2,%3}, [%4];"
        : "=r"(r[0]), "=r"(r[1]), "=r"(r[2]), "=r"(r[3]) : "r"(addr));
}
__device__ __forceinline__ void ldm_x2(u32* r, u32 addr) {
    asm volatile("ldmatrix.sync.aligned.m8n8.x2.shared.b16 {%0,%1}, [%2];"
        : "=r"(r[0]), "=r"(r[1]) : "r"(addr));
}
__device__ __forceinline__ void cp16(u32 smem, const void* g) {
    asm volatile("cp.async.cg.shared.global [%0], [%1], 16;" :: "r"(smem), "l"(g));
}
__device__ __forceinline__ void cp_commit() {
    asm volatile("cp.async.commit_group;" ::: "memory");
}
__device__ __forceinline__ void cp_wait0() {
    asm volatile("cp.async.wait_group 0;" ::: "memory");
}
__device__ __forceinline__ u32 smem_u32(const void* p) {
    u32 a;
    asm("{ .reg .u64 t; cvta.to.shared.u64 t, %1; cvt.u32.u64 %0, t; }"
        : "=r"(a) : "l"(p));
    return a;
}

// ---------------------------------------------------------------------------
// Prep: W -> bf16 hi/lo packed, fragment-ready.
// ---------------------------------------------------------------------------
__global__ __launch_bounds__(256) void prep_w_kernel(
    const float* __restrict__ Wq, const float* __restrict__ Wk,
    const float* __restrict__ Wv)
{
    int idx = blockIdx.x * 256 + threadIdx.x;
    int n = idx % 192, kk = idx / 192;
    const float* W = (n < 64) ? Wq : ((n < 128) ? Wk : Wv);
    int col = n & 63;
    float w0 = W[(size_t)(2 * kk) * HH + col];
    float w1 = W[(size_t)(2 * kk + 1) * HH + col];
    float h0 = bfh(w0), h1 = bfh(w1);
    g_wh[n * 512 + kk] = pkbf(h0, h1);
    g_wl[n * 512 + kk] = pkbf(w0 - h0, w1 - h1);
}

// ---------------------------------------------------------------------------
// Fused QKV projection, M=128 x N=192, K-chunk 32, single-wave grid(128).
// cp.async double-buffers raw fp32 X (stride 36 f) + packed W (stride 20 u32);
// X converted in-smem each chunk; bf16x3 via ldmatrix + mma.
// smem (u32): XRAW0 0 | XRAW1 4608 | XH 9216 | XL 11776 | W0 14336 | W1 22016
// ---------------------------------------------------------------------------
#define XR0   0
#define XR1   4608
#define PXH   9216
#define PXL   11776
#define PW0   14336
#define PW1   22016
#define WSTR  20
#define PROJ_SMEM_U32 29696   // 118784 B

__device__ __forceinline__ void stageX128(u32 sbyte, const float* g, int tid) {
    #pragma unroll
    for (int u = 0; u < 4; u++) {
        int idx = tid + u * 256;          // 1024 chunks: 128 rows x 8
        int row = idx >> 3, ch = idx & 7;
        cp16(sbyte + (u32)(row * 36 + ch * 4) * 4, g + (size_t)row * DIN + ch * 4);
    }
}
__device__ __forceinline__ void stageW(u32 sbyte, const u32* g, int tid) {
    #pragma unroll
    for (int u = 0; u < 3; u++) {
        int idx = tid + u * 256;          // 768 chunks: 192 rows x 4
        int row = idx >> 2, ch = idx & 3;
        cp16(sbyte + (u32)(row * WSTR + ch * 4) * 4, g + (size_t)row * 512 + ch * 4);
    }
}

__global__ __launch_bounds__(256) void proj_kernel(const float* __restrict__ x)
{
    extern __shared__ u32 sm[];
    const u32 sbx = smem_u32(sm);
    const int tid  = threadIdx.x;
    const int lane = tid & 31;
    const int wid  = tid >> 5;
    const int slab = wid >> 1, half = wid & 1;
    const int rr   = lane >> 2, q = lane & 3;
    const int m0   = blockIdx.x * 128;

    const int lane7 = lane & 7;
    const int arow  = lane7 + (lane & 8);
    const int acx4  = (lane & 16) ? 16 : 0;
    const int bex4  = (lane & 8) ? 16 : 0;

    u32 aH[2], aL[2];
    #pragma unroll
    for (int mt = 0; mt < 2; mt++) {
        aH[mt] = sbx + (u32)(PXH + (slab * 32 + mt * 16 + arow) * WSTR) * 4 + acx4;
        aL[mt] = aH[mt] + (PXL - PXH) * 4;
    }

    // preload chunk 0
    stageX128(sbx + XR0 * 4, x + (size_t)m0 * DIN, tid);
    stageW(sbx + PW0 * 4,                g_wh, tid);
    stageW(sbx + (PW0 + 3840) * 4,       g_wl, tid);
    cp_commit();

    float acc[2][12][4];
    #pragma unroll
    for (int mt = 0; mt < 2; mt++)
        #pragma unroll
        for (int i = 0; i < 12; i++)
            #pragma unroll
            for (int j = 0; j < 4; j++) acc[mt][i][j] = 0.f;

    for (int c = 0; c < 32; c++) {
        const int buf = c & 1;
        cp_wait0();
        __syncthreads();
        if (c < 31) {
            const u32 xr = (buf ? XR0 : XR1);
            const u32 wb = (buf ? PW0 : PW1);
            stageX128(sbx + xr * 4, x + (size_t)m0 * DIN + (c + 1) * 32, tid);
            stageW(sbx + wb * 4,               g_wh + (c + 1) * 16, tid);
            stageW(sbx + (wb + 3840) * 4,      g_wl + (c + 1) * 16, tid);
            cp_commit();
        }
        // convert raw X (current buf) -> packed XH/XL
        {
            const float* xraw = (const float*)(sm + (buf ? XR1 : XR0));
            u32* sxh = sm + PXH;
            u32* sxl = sm + PXL;
            #pragma unroll
            for (int u = 0; u < 2; u++) {
                int idx = tid + u * 256;         // 512 tasks: 128 rows x 4
                int row = idx >> 2, g3 = idx & 3;
                float4 v0 = *(const float4*)&xraw[row * 36 + g3 * 8];
                float4 v1 = *(const float4*)&xraw[row * 36 + g3 * 8 + 4];
                float h0 = bfh(v0.x), h1 = bfh(v0.y), h2 = bfh(v0.z), h3 = bfh(v0.w);
                float h4 = bfh(v1.x), h5 = bfh(v1.y), h6 = bfh(v1.z), h7 = bfh(v1.w);
                sxh[row * WSTR + g3 * 4]     = pkbf(h0, h1);
                sxh[row * WSTR + g3 * 4 + 1] = pkbf(h2, h3);
                sxh[row * WSTR + g3 * 4 + 2] = pkbf(h4, h5);
                sxh[row * WSTR + g3 * 4 + 3] = pkbf(h6, h7);
                sxl[row * WSTR + g3 * 4]     = pkbf(v0.x - h0, v0.y - h1);
                sxl[row * WSTR + g3 * 4 + 1] = pkbf(v0.z - h2, v0.w - h3);
                sxl[row * WSTR + g3 * 4 + 2] = pkbf(v1.x - h4, v1.y - h5);
                sxl[row * WSTR + g3 * 4 + 3] = pkbf(v1.z - h6, v1.w - h7);
            }
        }
        __syncthreads();

        const u32 wb = (u32)(buf ? PW1 : PW0);
        const u32 bH = sbx + (wb + (half * 96 + lane7) * WSTR) * 4 + bex4;
        const u32 bL = bH + 3840 * 4;

        #pragma unroll
        for (int kt = 0; kt < 2; kt++) {
            u32 ah0[4], al0[4], ah1[4], al1[4];
            ldm_x4(ah0, aH[0] + kt * 32);
            ldm_x4(al0, aL[0] + kt * 32);
            ldm_x4(ah1, aH[1] + kt * 32);
            ldm_x4(al1, aL[1] + kt * 32);
            #pragma unroll
            for (int nt = 0; nt < 12; nt++) {
                u32 bh[2], bl[2];
                ldm_x2(bh, bH + nt * (8 * WSTR * 4) + kt * 32);
                ldm_x2(bl, bL + nt * (8 * WSTR * 4) + kt * 32);
                mma16816(acc[0][nt], ah0, bh);
                mma16816(acc[0][nt], ah0, bl);
                mma16816(acc[0][nt], al0, bh);
                mma16816(acc[1][nt], ah1, bh);
                mma16816(acc[1][nt], ah1, bl);
                mma16816(acc[1][nt], al1, bh);
            }
        }
    }

    // epilogue: q/k packed rows; v written directly transposed (shfl-paired)
    u32* const GH[2] = {g_qh, g_kh};
    u32* const GL[2] = {g_ql, g_kl};
    #pragma unroll
    for (int mt = 0; mt < 2; mt++) {
        const int row0 = m0 + slab * 32 + mt * 16 + rr;
        #pragma unroll
        for (int nt = 0; nt < 12; nt++) {
            int colb = half * 96 + nt * 8;
            int mat = colb >> 6;
            float a0 = acc[mt][nt][0], a1 = acc[mt][nt][1];
            float a2 = acc[mt][nt][2], a3 = acc[mt][nt][3];
            if (mat < 2) {
                float s = (mat == 1) ? 0.125f : 1.f;
                a0 *= s; a1 *= s; a2 *= s; a3 *= s;
                int hqb = (colb & 63) >> 1;
                float h0 = bfh(a0), h1 = bfh(a1), h2 = bfh(a2), h3 = bfh(a3);
                GH[mat][(size_t)row0 * 32 + hqb + q]       = pkbf(h0, h1);
                GL[mat][(size_t)row0 * 32 + hqb + q]       = pkbf(a0 - h0, a1 - h1);
                GH[mat][(size_t)(row0 + 8) * 32 + hqb + q] = pkbf(h2, h3);
                GL[mat][(size_t)(row0 + 8) * 32 + hqb + q] = pkbf(a2 - h2, a3 - h3);
            } else {
                // V: pair rows (r, r+1) via lane^4 (rr parity), write transposed
                float p0 = __shfl_xor_sync(0xffffffffu, a0, 4);
                float p1 = __shfl_xor_sync(0xffffffffu, a1, 4);
                float p2 = __shfl_xor_sync(0xffffffffu, a2, 4);
                float p3 = __shfl_xor_sync(0xffffffffu, a3, 4);
                if (!(rr & 1)) {
                    int bb2 = row0 >> 11;
                    int sp  = (row0 & 2047) >> 1;
                    int vc  = (colb - 128) + 2 * q;
                    size_t base0 = ((size_t)(bb2 * 64 + vc)) * 1024;
                    size_t base1 = base0 + 1024;
                    float h, hp;
                    h = bfh(a0); hp = bfh(p0);
                    g_vth[base0 + sp] = pkbf(h, hp);
                    g_vtl[base0 + sp] = pkbf(a0 - h, p0 - hp);
                    h = bfh(a1); hp = bfh(p1);
                    g_vth[base1 + sp] = pkbf(h, hp);
                    g_vtl[base1 + sp] = pkbf(a1 - h, p1 - hp);
                    h = bfh(a2); hp = bfh(p2);
                    g_vth[base0 + sp + 4] = pkbf(h, hp);
                    g_vtl[base0 + sp + 4] = pkbf(a2 - h, p2 - hp);
                    h = bfh(a3); hp = bfh(p3);
                    g_vth[base1 + sp + 4] = pkbf(h, hp);
                    g_vtl[base1 + sp + 4] = pkbf(a3 - h, p3 - hp);
                }
            }
        }
    }
}

// ---------------------------------------------------------------------------
// Flash attention, triangle-paired CTAs, K fragments register-resident.
// ---------------------------------------------------------------------------
#define KOFF(t, l)  ((t) * 4608 + (l) * 2304)
#define QOFF(bf, l) (9216 + (bf) * 4608 + (l) * 2304)
#define VOFF(bf, l) (18432 + (bf) * 4608 + (l) * 2304)
#define ATTN_SMEM_U32 27904   // 111616 B

__device__ __forceinline__ void stage64(u32 sbyte, const u32* g, int gstride, int tid) {
    #pragma unroll
    for (int u = 0; u < 2; u++) {
        int idx = tid + u * 256;      // 512 16B chunks
        int row = idx >> 3, ch = idx & 7;
        cp16(sbyte + (u32)(row * PST + ch * 4) * 4, g + (size_t)row * gstride + ch * 4);
    }
}

__device__ __forceinline__ void online_update(
    float (&sacc)[4][4], float& m_lo, float& m_hi, float& l_lo, float& l_hi,
    float (&o)[8][4], u32 (&pah)[2][4], u32 (&pal)[2][4])
{
    float mx0 = -INFINITY, mx1 = -INFINITY;
    #pragma unroll
    for (int nt = 0; nt < 4; nt++) {
        mx0 = fmaxf(mx0, fmaxf(sacc[nt][0], sacc[nt][1]));
        mx1 = fmaxf(mx1, fmaxf(sacc[nt][2], sacc[nt][3]));
    }
    mx0 = fmaxf(mx0, __shfl_xor_sync(0xffffffffu, mx0, 1));
    mx0 = fmaxf(mx0, __shfl_xor_sync(0xffffffffu, mx0, 2));
    mx1 = fmaxf(mx1, __shfl_xor_sync(0xffffffffu, mx1, 1));
    mx1 = fmaxf(mx1, __shfl_xor_sync(0xffffffffu, mx1, 2));
    float mn0 = fmaxf(m_lo, mx0), mn1 = fmaxf(m_hi, mx1);
    float sum0 = 0.f, sum1 = 0.f;
    #pragma unroll
    for (int nt = 0; nt < 4; nt++) {
        sacc[nt][0] = __expf(fmaxf(sacc[nt][0] - mn0, -88.f));
        sacc[nt][1] = __expf(fmaxf(sacc[nt][1] - mn0, -88.f));
        sacc[nt][2] = __expf(fmaxf(sacc[nt][2] - mn1, -88.f));
        sacc[nt][3] = __expf(fmaxf(sacc[nt][3] - mn1, -88.f));
        sum0 += sacc[nt][0] + sacc[nt][1];
        sum1 += sacc[nt][2] + sacc[nt][3];
    }
    sum0 += __shfl_xor_sync(0xffffffffu, sum0, 1);
    sum0 += __shfl_xor_sync(0xffffffffu, sum0, 2);
    sum1 += __shfl_xor_sync(0xffffffffu, sum1, 1);
    sum1 += __shfl_xor_sync(0xffffffffu, sum1, 2);
    float cf0 = __expf(fmaxf(m_lo - mn0, -88.f));
    float cf1 = __expf(fmaxf(m_hi - mn1, -88.f));
    l_lo = l_lo * cf0 + sum0; l_hi = l_hi * cf1 + sum1;
    m_lo = mn0; m_hi = mn1;
    #pragma unroll
    for (int nt = 0; nt < 8; nt++) {
        o[nt][0] *= cf0; o[nt][1] *= cf0;
        o[nt][2] *= cf1; o[nt][3] *= cf1;
    }
    #pragma unroll
    for (int kp = 0; kp < 2; kp++) {
        float p00 = sacc[2*kp][0],   p01 = sacc[2*kp][1];
        float p02 = sacc[2*kp][2],   p03 = sacc[2*kp][3];
        float p10 = sacc[2*kp+1][0], p11 = sacc[2*kp+1][1];
        float p12 = sacc[2*kp+1][2], p13 = sacc[2*kp+1][3];
        float h00 = bfh(p00), h01 = bfh(p01), h02 = bfh(p02), h03 = bfh(p03);
        float h10 = bfh(p10), h11 = bfh(p11), h12 = bfh(p12), h13 = bfh(p13);
        pah[kp][0] = pkbf(h00, h01);
        pah[kp][1] = pkbf(h02, h03);
        pah[kp][2] = pkbf(h10, h11);
        pah[kp][3] = pkbf(h12, h13);
        pal[kp][0] = pkbf(p00 - h00, p01 - h01);
        pal[kp][1] = pkbf(p02 - h02, p03 - h03);
        pal[kp][2] = pkbf(p10 - h10, p11 - h11);
        pal[kp][3] = pkbf(p12 - h12, p13 - h13);
    }
}

__device__ __forceinline__ void merge_write(
    float (&o)[8][4], float m_lo, float m_hi, float l_lo, float l_hi,
    float* mlbuf, float* obuf, int slab, int half, int rr, int q,
    float* __restrict__ out, int b, int t0)
{
    __syncthreads();
    if (q == 0) {
        int base = (slab * 2 + half) * 16;
        mlbuf[(base + rr) * 2]         = m_lo;
        mlbuf[(base + rr) * 2 + 1]     = l_lo;
        mlbuf[(base + rr + 8) * 2]     = m_hi;
        mlbuf[(base + rr + 8) * 2 + 1] = l_hi;
    }
    __syncthreads();
    int ob = (slab * 2 + (1 - half)) * 16;
    float mo0 = mlbuf[(ob + rr) * 2],     lo0 = mlbuf[(ob + rr) * 2 + 1];
    float mo1 = mlbuf[(ob + rr + 8) * 2], lo1 = mlbuf[(ob + rr + 8) * 2 + 1];
    float M0 = fmaxf(m_lo, mo0), M1 = fmaxf(m_hi, mo1);
    float f0 = __expf(fmaxf(m_lo - M0, -88.f));
    float f1 = __expf(fmaxf(m_hi - M1, -88.f));
    float g0 = __expf(fmaxf(mo0 - M0, -88.f));
    float g1 = __expf(fmaxf(mo1 - M1, -88.f));
    float L0 = l_lo * f0 + lo0 * g0;
    float L1 = l_hi * f1 + lo1 * g1;
    #pragma unroll
    for (int nt = 0; nt < 8; nt++) {
        o[nt][0] *= f0; o[nt][1] *= f0;
        o[nt][2] *= f1; o[nt][3] *= f1;
    }
    if (half == 1) {
        #pragma unroll
        for (int nt = 0; nt < 8; nt++) {
            int cb = nt * 8 + 2 * q;
            obuf[(slab * 16 + rr) * 64 + cb]         = o[nt][0];
            obuf[(slab * 16 + rr) * 64 + cb + 1]     = o[nt][1];
            obuf[(slab * 16 + rr + 8) * 64 + cb]     = o[nt][2];
            obuf[(slab * 16 + rr + 8) * 64 + cb + 1] = o[nt][3];
        }
    }
    __syncthreads();
    if (half == 0) {
        float i0 = 1.f / L0, i1 = 1.f / L1;
        size_t rb = ((size_t)b * TT + t0 + slab * 16 + rr) * 64;
        #pragma unroll
        for (int nt = 0; nt < 8; nt++) {
            int cb = nt * 8 + 2 * q;
            float2 r1;
            r1.x = (o[nt][0] + obuf[(slab * 16 + rr) * 64 + cb]) * i0;
            r1.y = (o[nt][1] + obuf[(slab * 16 + rr) * 64 + cb + 1]) * i0;
            *(float2*)(out + rb + cb) = r1;
            float2 r2;
            r2.x = (o[nt][2] + obuf[(slab * 16 + rr + 8) * 64 + cb]) * i1;
            r2.y = (o[nt][3] + obuf[(slab * 16 + rr + 8) * 64 + cb + 1]) * i1;
            *(float2*)(out + rb + 8 * 64 + cb) = r2;
        }
    }
}

__global__ __launch_bounds__(256) void attn_kernel(float* __restrict__ out)
{
    extern __shared__ u32 sm[];
    float* mlbuf = (float*)(sm + 27648);
    float* obuf  = (float*)(sm + 9216);

    const int tid  = threadIdx.x;
    const int wid  = tid >> 5, lane = tid & 31;
    const int slab = wid >> 1, half = wid & 1;
    const int rr   = lane >> 2, q = lane & 3;
    const int b    = blockIdx.y;
    const int bx   = blockIdx.x;          // tile A = bx, tile B = 31-bx
    const int tB   = 31 - bx;
    const int last = tB;

    const u32 sb = smem_u32(sm);
    const int lane7 = lane & 7;
    const int arow  = lane7 + (lane & 8);
    const int acx4  = (lane & 16) ? 16 : 0;
    const int bex4  = (lane & 8) ? 16 : 0;

    // stage K (both tiles) + Q/V(st=0)
    stage64(sb + (u32)KOFF(0,0) * 4, g_kh + ((size_t)b * TT + bx * 64) * 32, 32, tid);
    stage64(sb + (u32)KOFF(0,1) * 4, g_kl + ((size_t)b * TT + bx * 64) * 32, 32, tid);
    stage64(sb + (u32)KOFF(1,0) * 4, g_kh + ((size_t)b * TT + tB * 64) * 32, 32, tid);
    stage64(sb + (u32)KOFF(1,1) * 4, g_kl + ((size_t)b * TT + tB * 64) * 32, 32, tid);
    stage64(sb + (u32)QOFF(0,0) * 4, g_qh + (size_t)b * TT * 32, 32, tid);
    stage64(sb + (u32)QOFF(0,1) * 4, g_ql + (size_t)b * TT * 32, 32, tid);
    stage64(sb + (u32)VOFF(0,0) * 4, g_vth + (size_t)b * 65536, 1024, tid);
    stage64(sb + (u32)VOFF(0,1) * 4, g_vtl + (size_t)b * 65536, 1024, tid);
    cp_commit();
    cp_wait0();
    __syncthreads();

    // hoist K fragments to registers: [tile][hl][kt][4]
    u32 kf[2][2][4][4];
    #pragma unroll
    for (int t = 0; t < 2; t++)
        #pragma unroll
        for (int l = 0; l < 2; l++) {
            u32 base = sb + (u32)(KOFF(t,l) + (slab * 16 + arow) * PST) * 4 + acx4;
            #pragma unroll
            for (int kt = 0; kt < 4; kt++)
                ldm_x4(kf[t][l][kt], base + kt * 32);
        }

    float oA[8][4], oB[8][4];
    #pragma unroll
    for (int i = 0; i < 8; i++)
        #pragma unroll
        for (int j = 0; j < 4; j++) { oA[i][j] = 0.f; oB[i][j] = 0.f; }
    float mA0 = -INFINITY, mA1 = -INFINITY, lA0 = 0.f, lA1 = 0.f;
    float mB0 = -INFINITY, mB1 = -INFINITY, lB0 = 0.f, lB1 = 0.f;

    for (int st = 0; st <= last; st++) {
        const int buf = st & 1;
        if (st > 0) { cp_wait0(); __syncthreads(); }
        if (st < last) {
            int nb = buf ^ 1, s1 = st + 1;
            stage64(sb + (u32)QOFF(nb,0) * 4, g_qh + ((size_t)b * TT + s1 * 64) * 32, 32, tid);
            stage64(sb + (u32)QOFF(nb,1) * 4, g_ql + ((size_t)b * TT + s1 * 64) * 32, 32, tid);
            stage64(sb + (u32)VOFF(nb,0) * 4, g_vth + (size_t)b * 65536 + s1 * 32, 1024, tid);
            stage64(sb + (u32)VOFF(nb,1) * 4, g_vtl + (size_t)b * 65536 + s1 * 32, 1024, tid);
            cp_commit();
        }
        const bool actA = (st <= bx);
        const u32 qB  = sb + (u32)(QOFF(buf,0) + (half * 32 + lane7) * PST) * 4 + bex4;
        const u32 qBl = qB + 2304 * 4;
        const u32 vB  = sb + (u32)(VOFF(buf,0) + lane7 * PST + half * 16) * 4 + bex4;
        const u32 vBl = vB + 2304 * 4;

        // ---- S for both tiles (K from registers) ----
        float sA[4][4], sB4[4][4];
        #pragma unroll
        for (int i = 0; i < 4; i++)
            #pragma unroll
            for (int j = 0; j < 4; j++) { sA[i][j] = 0.f; sB4[i][j] = 0.f; }
        #pragma unroll
        for (int kt = 0; kt < 4; kt++) {
            #pragma unroll
            for (int nt = 0; nt < 4; nt++) {
                u32 bh[2], bl[2];
                ldm_x2(bh, qB  + nt * (8 * PST * 4) + kt * 32);
                ldm_x2(bl, qBl + nt * (8 * PST * 4) + kt * 32);
                if (actA) {
                    mma16816(sA[nt], kf[0][0][kt], bh);
                    mma16816(sA[nt], kf[0][0][kt], bl);
                    mma16816(sA[nt], kf[0][1][kt], bh);
                }
                mma16816(sB4[nt], kf[1][0][kt], bh);
                mma16816(sB4[nt], kf[1][0][kt], bl);
                mma16816(sB4[nt], kf[1][1][kt], bh);
            }
        }

        const int s0 = st * 64;
        u32 pahA[2][4], palA[2][4], pahB[2][4], palB[2][4];
        if (actA) {
            if (st == bx) {
                int tlo = bx * 64 + slab * 16 + rr, thi = tlo + 8;
                #pragma unroll
                for (int nt = 0; nt < 4; nt++) {
                    int sc = s0 + half * 32 + nt * 8 + 2 * q;
                    if (sc > tlo)     sA[nt][0] = -INFINITY;
                    if (sc + 1 > tlo) sA[nt][1] = -INFINITY;
                    if (sc > thi)     sA[nt][2] = -INFINITY;
                    if (sc + 1 > thi) sA[nt][3] = -INFINITY;
                }
            }
            online_update(sA, mA0, mA1, lA0, lA1, oA, pahA, palA);
        }
        if (st == tB) {
            int tlo = tB * 64 + slab * 16 + rr, thi = tlo + 8;
            #pragma unroll
            for (int nt = 0; nt < 4; nt++) {
                int sc = s0 + half * 32 + nt * 8 + 2 * q;
                if (sc > tlo)     sB4[nt][0] = -INFINITY;
                if (sc + 1 > tlo) sB4[nt][1] = -INFINITY;
                if (sc > thi)     sB4[nt][2] = -INFINITY;
                if (sc + 1 > thi) sB4[nt][3] = -INFINITY;
            }
        }
        online_update(sB4, mB0, mB1, lB0, lB1, oB, pahB, palB);

        // ---- O += P.V (V fragments shared between tiles) ----
        #pragma unroll
        for (int kp = 0; kp < 2; kp++) {
            #pragma unroll
            for (int nt = 0; nt < 8; nt++) {
                u32 vh2[2], vl2[2];
                ldm_x2(vh2, vB  + nt * (8 * PST * 4) + kp * 32);
                ldm_x2(vl2, vBl + nt * (8 * PST * 4) + kp * 32);
                if (actA) {
                    mma16816(oA[nt], pahA[kp], vh2);
                    mma16816(oA[nt], pahA[kp], vl2);
                    mma16816(oA[nt], palA[kp], vh2);
                }
                mma16816(oB[nt], pahB[kp], vh2);
                mma16816(oB[nt], pahB[kp], vl2);
                mma16816(oB[nt], palB[kp], vh2);
            }
        }
    }

    merge_write(oA, mA0, mA1, lA0, lA1, mlbuf, obuf, slab, half, rr, q, out, b, bx * 64);
    merge_write(oB, mB0, mB1, lB0, lB1, mlbuf, obuf, slab, half, rr, q, out, b, tB * 64);
}

// ---------------------------------------------------------------------------
extern "C" void kernel_launch(void* const* d_in, const int* in_sizes, int n_in,
                              void* d_out, int out_size)
{
    const float* x  = (const float*)d_in[0];
    const float* Wq = (const float*)d_in[1];
    const float* Wk = (const float*)d_in[2];
    const float* Wv = (const float*)d_in[3];
    float* out = (float*)d_out;

    prep_w_kernel<<<384, 256>>>(Wq, Wk, Wv);

    cudaFuncSetAttribute(proj_kernel,
                         cudaFuncAttributeMaxDynamicSharedMemorySize,
                         PROJ_SMEM_U32 * 4);
    proj_kernel<<<128, 256, PROJ_SMEM_U32 * 4>>>(x);

    cudaFuncSetAttribute(attn_kernel,
                         cudaFuncAttributeMaxDynamicSharedMemorySize,
                         ATTN_SMEM_U32 * 4);
    dim3 grid(16, BB);
    attn_kernel<<<grid, 256, ATTN_SMEM_U32 * 4>>>(out);
}

// round 12
// speedup vs baseline: 1.2407x; 1.0096x over previous
#include <cuda_runtime.h>
#include <cuda_bf16.h>
#include <math.h>

#define BB   8
#define TT   2048
#define DIN  1024
#define HH   64
#define BT   (BB*TT)
#define PST  36      // attn smem row stride in u32 (144B) -> conflict-free ldmatrix

typedef unsigned int u32;

// Packed bf16x2 hi/lo scratch (q,k) and transposed v, prepped weights.
__device__ __align__(16) u32 g_qh[BT*32];
__device__ __align__(16) u32 g_ql[BT*32];
__device__ __align__(16) u32 g_kh[BT*32];
__device__ __align__(16) u32 g_kl[BT*32];
// V transposed: [b][h 0..63][sp 0..1023], u32 = pack(v[2sp][h], v[2sp+1][h])
__device__ __align__(16) u32 g_vth[BB*64*1024];
__device__ __align__(16) u32 g_vtl[BB*64*1024];
// W fragment-ready: [n 0..191][kk 0..511] u32 = pack(W[2kk][n], W[2kk+1][n])
__device__ __align__(16) u32 g_wh[192*512];
__device__ __align__(16) u32 g_wl[192*512];

// ---- helpers ---------------------------------------------------------------
__device__ __forceinline__ u32 pkbf(float lo, float hi) {
    u32 r; asm("cvt.rn.bf16x2.f32 %0, %1, %2;" : "=r"(r) : "f"(hi), "f"(lo));
    return r;
}
__device__ __forceinline__ float bfh(float x) {
    return __bfloat162float(__float2bfloat16(x));
}
__device__ __forceinline__ void mma16816(float* c, const u32* a, const u32* b) {
    asm volatile(
        "mma.sync.aligned.m16n8k16.row.col.f32.bf16.bf16.f32 "
        "{%0,%1,%2,%3}, {%4,%5,%6,%7}, {%8,%9}, {%0,%1,%2,%3};"
        : "+f"(c[0]), "+f"(c[1]), "+f"(c[2]), "+f"(c[3])
        : "r"(a[0]), "r"(a[1]), "r"(a[2]), "r"(a[3]), "r"(b[0]), "r"(b[1]));
}
__device__ __forceinline__ void ldm_x4(u32* r, u32 addr) {
    asm volatile("ldmatrix.sync.aligned.m8n8.x4.shared.b16 {%0,%1,%2,%3}, [%4];"
        : "=r"(r[0]), "=r"(r[1]), "=r"(r[2]), "=r"(r[3]) : "r"(addr));
}
__device__ __forceinline__ void ldm_x2(u32* r, u32 addr) {
    asm volatile("ldmatrix.sync.aligned.m8n8.x2.shared.b16 {%0,%1}, [%2];"
        : "=r"(r[0]), "=r"(r[1]) : "r"(addr));
}
__device__ __forceinline__ void cp16(u32 smem, const void* g) {
    asm volatile("cp.async.cg.shared.global [%0], [%1], 16;" :: "r"(smem), "l"(g));
}
__device__ __forceinline__ void cp_commit() {
    asm volatile("cp.async.commit_group;" ::: "memory");
}
__device__ __forceinline__ void cp_wait0() {
    asm volatile("cp.async.wait_group 0;" ::: "memory");
}
__device__ __forceinline__ u32 smem_u32(const void* p) {
    u32 a;
    asm("{ .reg .u64 t; cvta.to.shared.u64 t, %1; cvt.u32.u64 %0, t; }"
        : "=r"(a) : "l"(p));
    return a;
}

// ---------------------------------------------------------------------------
// Prep: W -> bf16 hi/lo packed, fragment-ready.
// ---------------------------------------------------------------------------
__global__ __launch_bounds__(256) void prep_w_kernel(
    const float* __restrict__ Wq, const float* __restrict__ Wk,
    const float* __restrict__ Wv)
{
    int idx = blockIdx.x * 256 + threadIdx.x;
    int n = idx % 192, kk = idx / 192;
    const float* W = (n < 64) ? Wq : ((n < 128) ? Wk : Wv);
    int col = n & 63;
    float w0 = W[(size_t)(2 * kk) * HH + col];
    float w1 = W[(size_t)(2 * kk + 1) * HH + col];
    float h0 = bfh(w0), h1 = bfh(w1);
    g_wh[n * 512 + kk] = pkbf(h0, h1);
    g_wl[n * 512 + kk] = pkbf(w0 - h0, w1 - h1);
}

// ---------------------------------------------------------------------------
// Fused QKV projection, M=128 x N=192, K-chunk 32, single-wave grid(128),
// 512 threads / 16 warps (slab 0..3 x quarter-column 0..3) for latency hiding.
// smem (u32): XRAW0 0 | XRAW1 4608 | XH 9216 | XL 11776 | W0 14336 | W1 22016
// ---------------------------------------------------------------------------
#define XR0   0
#define XR1   4608
#define PXH   9216
#define PXL   11776
#define PW0   14336
#define PW1   22016
#define WSTR  20
#define PROJ_SMEM_U32 29696   // 118784 B

__device__ __forceinline__ void stageX128(u32 sbyte, const float* g, int tid) {
    #pragma unroll
    for (int u = 0; u < 2; u++) {
        int idx = tid + u * 512;          // 1024 chunks: 128 rows x 8
        int row = idx >> 3, ch = idx & 7;
        cp16(sbyte + (u32)(row * 36 + ch * 4) * 4, g + (size_t)row * DIN + ch * 4);
    }
}
__device__ __forceinline__ void stageW(u32 sbyte, const u32* g, int tid) {
    {
        int row = tid >> 2, ch = tid & 3;     // chunks 0..511
        cp16(sbyte + (u32)(row * WSTR + ch * 4) * 4, g + (size_t)row * 512 + ch * 4);
    }
    int idx = tid + 512;                      // chunks 512..767
    if (idx < 768) {
        int row = idx >> 2, ch = idx & 3;
        cp16(sbyte + (u32)(row * WSTR + ch * 4) * 4, g + (size_t)row * 512 + ch * 4);
    }
}

__global__ __launch_bounds__(512) void proj_kernel(const float* __restrict__ x)
{
    extern __shared__ u32 sm[];
    const u32 sbx = smem_u32(sm);
    const int tid  = threadIdx.x;
    const int lane = tid & 31;
    const int wid  = tid >> 5;               // 0..15
    const int slab = wid >> 2, qc = wid & 3; // 4 slabs x 4 quarter-columns
    const int rr   = lane >> 2, q = lane & 3;
    const int m0   = blockIdx.x * 128;

    const int lane7 = lane & 7;
    const int arow  = lane7 + (lane & 8);
    const int acx4  = (lane & 16) ? 16 : 0;
    const int bex4  = (lane & 8) ? 16 : 0;

    u32 aH[2], aL[2];
    #pragma unroll
    for (int mt = 0; mt < 2; mt++) {
        aH[mt] = sbx + (u32)(PXH + (slab * 32 + mt * 16 + arow) * WSTR) * 4 + acx4;
        aL[mt] = aH[mt] + (PXL - PXH) * 4;
    }

    // preload chunk 0
    stageX128(sbx + XR0 * 4, x + (size_t)m0 * DIN, tid);
    stageW(sbx + PW0 * 4,                g_wh, tid);
    stageW(sbx + (PW0 + 3840) * 4,       g_wl, tid);
    cp_commit();

    float acc[2][6][4];
    #pragma unroll
    for (int mt = 0; mt < 2; mt++)
        #pragma unroll
        for (int i = 0; i < 6; i++)
            #pragma unroll
            for (int j = 0; j < 4; j++) acc[mt][i][j] = 0.f;

    for (int c = 0; c < 32; c++) {
        const int buf = c & 1;
        cp_wait0();
        __syncthreads();
        if (c < 31) {
            const u32 xr = (buf ? XR0 : XR1);
            const u32 wb = (buf ? PW0 : PW1);
            stageX128(sbx + xr * 4, x + (size_t)m0 * DIN + (c + 1) * 32, tid);
            stageW(sbx + wb * 4,               g_wh + (c + 1) * 16, tid);
            stageW(sbx + (wb + 3840) * 4,      g_wl + (c + 1) * 16, tid);
            cp_commit();
        }
        // convert raw X (current buf) -> packed XH/XL : 512 tasks, one each
        {
            const float* xraw = (const float*)(sm + (buf ? XR1 : XR0));
            u32* sxh = sm + PXH;
            u32* sxl = sm + PXL;
            int row = tid >> 2, g3 = tid & 3;
            float4 v0 = *(const float4*)&xraw[row * 36 + g3 * 8];
            float4 v1 = *(const float4*)&xraw[row * 36 + g3 * 8 + 4];
            float h0 = bfh(v0.x), h1 = bfh(v0.y), h2 = bfh(v0.z), h3 = bfh(v0.w);
            float h4 = bfh(v1.x), h5 = bfh(v1.y), h6 = bfh(v1.z), h7 = bfh(v1.w);
            sxh[row * WSTR + g3 * 4]     = pkbf(h0, h1);
            sxh[row * WSTR + g3 * 4 + 1] = pkbf(h2, h3);
            sxh[row * WSTR + g3 * 4 + 2] = pkbf(h4, h5);
            sxh[row * WSTR + g3 * 4 + 3] = pkbf(h6, h7);
            sxl[row * WSTR + g3 * 4]     = pkbf(v0.x - h0, v0.y - h1);
            sxl[row * WSTR + g3 * 4 + 1] = pkbf(v0.z - h2, v0.w - h3);
            sxl[row * WSTR + g3 * 4 + 2] = pkbf(v1.x - h4, v1.y - h5);
            sxl[row * WSTR + g3 * 4 + 3] = pkbf(v1.z - h6, v1.w - h7);
        }
        __syncthreads();

        const u32 wb = (u32)(buf ? PW1 : PW0);
        const u32 bH = sbx + (wb + (qc * 48 + lane7) * WSTR) * 4 + bex4;
        const u32 bL = bH + 3840 * 4;

        #pragma unroll
        for (int kt = 0; kt < 2; kt++) {
            u32 ah0[4], al0[4], ah1[4], al1[4];
            ldm_x4(ah0, aH[0] + kt * 32);
            ldm_x4(al0, aL[0] + kt * 32);
            ldm_x4(ah1, aH[1] + kt * 32);
            ldm_x4(al1, aL[1] + kt * 32);
            #pragma unroll
            for (int nt = 0; nt < 6; nt++) {
                u32 bh[2], bl[2];
                ldm_x2(bh, bH + nt * (8 * WSTR * 4) + kt * 32);
                ldm_x2(bl, bL + nt * (8 * WSTR * 4) + kt * 32);
                mma16816(acc[0][nt], ah0, bh);
                mma16816(acc[0][nt], ah0, bl);
                mma16816(acc[0][nt], al0, bh);
                mma16816(acc[1][nt], ah1, bh);
                mma16816(acc[1][nt], ah1, bl);
                mma16816(acc[1][nt], al1, bh);
            }
        }
    }

    // epilogue: q/k packed rows; v written directly transposed (shfl-paired)
    u32* const GH[2] = {g_qh, g_kh};
    u32* const GL[2] = {g_ql, g_kl};
    #pragma unroll
    for (int mt = 0; mt < 2; mt++) {
        const int row0 = m0 + slab * 32 + mt * 16 + rr;
        #pragma unroll
        for (int nt = 0; nt < 6; nt++) {
            int colb = qc * 48 + nt * 8;
            int mat = colb >> 6;
            float a0 = acc[mt][nt][0], a1 = acc[mt][nt][1];
            float a2 = acc[mt][nt][2], a3 = acc[mt][nt][3];
            if (mat < 2) {
                float s = (mat == 1) ? 0.125f : 1.f;
                a0 *= s; a1 *= s; a2 *= s; a3 *= s;
                int hqb = (colb & 63) >> 1;
                float h0 = bfh(a0), h1 = bfh(a1), h2 = bfh(a2), h3 = bfh(a3);
                GH[mat][(size_t)row0 * 32 + hqb + q]       = pkbf(h0, h1);
                GL[mat][(size_t)row0 * 32 + hqb + q]       = pkbf(a0 - h0, a1 - h1);
                GH[mat][(size_t)(row0 + 8) * 32 + hqb + q] = pkbf(h2, h3);
                GL[mat][(size_t)(row0 + 8) * 32 + hqb + q] = pkbf(a2 - h2, a3 - h3);
            } else {
                // V: pair rows (r, r+1) via lane^4 (rr parity), write transposed
                float p0 = __shfl_xor_sync(0xffffffffu, a0, 4);
                float p1 = __shfl_xor_sync(0xffffffffu, a1, 4);
                float p2 = __shfl_xor_sync(0xffffffffu, a2, 4);
                float p3 = __shfl_xor_sync(0xffffffffu, a3, 4);
                if (!(rr & 1)) {
                    int bb2 = row0 >> 11;
                    int sp  = (row0 & 2047) >> 1;
                    int vc  = (colb - 128) + 2 * q;
                    size_t base0 = ((size_t)(bb2 * 64 + vc)) * 1024;
                    size_t base1 = base0 + 1024;
                    float h, hp;
                    h = bfh(a0); hp = bfh(p0);
                    g_vth[base0 + sp] = pkbf(h, hp);
                    g_vtl[base0 + sp] = pkbf(a0 - h, p0 - hp);
                    h = bfh(a1); hp = bfh(p1);
                    g_vth[base1 + sp] = pkbf(h, hp);
                    g_vtl[base1 + sp] = pkbf(a1 - h, p1 - hp);
                    h = bfh(a2); hp = bfh(p2);
                    g_vth[base0 + sp + 4] = pkbf(h, hp);
                    g_vtl[base0 + sp + 4] = pkbf(a2 - h, p2 - hp);
                    h = bfh(a3); hp = bfh(p3);
                    g_vth[base1 + sp + 4] = pkbf(h, hp);
                    g_vtl[base1 + sp + 4] = pkbf(a3 - h, p3 - hp);
                }
            }
        }
    }
}

// ---------------------------------------------------------------------------
// Flash attention, triangle-paired CTAs, K fragments register-resident.
// (unchanged from R11 / 155.6us)
// ---------------------------------------------------------------------------
#define KOFF(t, l)  ((t) * 4608 + (l) * 2304)
#define QOFF(bf, l) (9216 + (bf) * 4608 + (l) * 2304)
#define VOFF(bf, l) (18432 + (bf) * 4608 + (l) * 2304)
#define ATTN_SMEM_U32 27904   // 111616 B

__device__ __forceinline__ void stage64(u32 sbyte, const u32* g, int gstride, int tid) {
    #pragma unroll
    for (int u = 0; u < 2; u++) {
        int idx = tid + u * 256;      // 512 16B chunks
        int row = idx >> 3, ch = idx & 7;
        cp16(sbyte + (u32)(row * PST + ch * 4) * 4, g + (size_t)row * gstride + ch * 4);
    }
}

__device__ __forceinline__ void online_update(
    float (&sacc)[4][4], float& m_lo, float& m_hi, float& l_lo, float& l_hi,
    float (&o)[8][4], u32 (&pah)[2][4], u32 (&pal)[2][4])
{
    float mx0 = -INFINITY, mx1 = -INFINITY;
    #pragma unroll
    for (int nt = 0; nt < 4; nt++) {
        mx0 = fmaxf(mx0, fmaxf(sacc[nt][0], sacc[nt][1]));
        mx1 = fmaxf(mx1, fmaxf(sacc[nt][2], sacc[nt][3]));
    }
    mx0 = fmaxf(mx0, __shfl_xor_sync(0xffffffffu, mx0, 1));
    mx0 = fmaxf(mx0, __shfl_xor_sync(0xffffffffu, mx0, 2));
    mx1 = fmaxf(mx1, __shfl_xor_sync(0xffffffffu, mx1, 1));
    mx1 = fmaxf(mx1, __shfl_xor_sync(0xffffffffu, mx1, 2));
    float mn0 = fmaxf(m_lo, mx0), mn1 = fmaxf(m_hi, mx1);
    float sum0 = 0.f, sum1 = 0.f;
    #pragma unroll
    for (int nt = 0; nt < 4; nt++) {
        sacc[nt][0] = __expf(fmaxf(sacc[nt][0] - mn0, -88.f));
        sacc[nt][1] = __expf(fmaxf(sacc[nt][1] - mn0, -88.f));
        sacc[nt][2] = __expf(fmaxf(sacc[nt][2] - mn1, -88.f));
        sacc[nt][3] = __expf(fmaxf(sacc[nt][3] - mn1, -88.f));
        sum0 += sacc[nt][0] + sacc[nt][1];
        sum1 += sacc[nt][2] + sacc[nt][3];
    }
    sum0 += __shfl_xor_sync(0xffffffffu, sum0, 1);
    sum0 += __shfl_xor_sync(0xffffffffu, sum0, 2);
    sum1 += __shfl_xor_sync(0xffffffffu, sum1, 1);
    sum1 += __shfl_xor_sync(0xffffffffu, sum1, 2);
    float cf0 = __expf(fmaxf(m_lo - mn0, -88.f));
    float cf1 = __expf(fmaxf(m_hi - mn1, -88.f));
    l_lo = l_lo * cf0 + sum0; l_hi = l_hi * cf1 + sum1;
    m_lo = mn0; m_hi = mn1;
    #pragma unroll
    for (int nt = 0; nt < 8; nt++) {
        o[nt][0] *= cf0; o[nt][1] *= cf0;
        o[nt][2] *= cf1; o[nt][3] *= cf1;
    }
    #pragma unroll
    for (int kp = 0; kp < 2; kp++) {
        float p00 = sacc[2*kp][0],   p01 = sacc[2*kp][1];
        float p02 = sacc[2*kp][2],   p03 = sacc[2*kp][3];
        float p10 = sacc[2*kp+1][0], p11 = sacc[2*kp+1][1];
        float p12 = sacc[2*kp+1][2], p13 = sacc[2*kp+1][3];
        float h00 = bfh(p00), h01 = bfh(p01), h02 = bfh(p02), h03 = bfh(p03);
        float h10 = bfh(p10), h11 = bfh(p11), h12 = bfh(p12), h13 = bfh(p13);
        pah[kp][0] = pkbf(h00, h01);
        pah[kp][1] = pkbf(h02, h03);
        pah[kp][2] = pkbf(h10, h11);
        pah[kp][3] = pkbf(h12, h13);
        pal[kp][0] = pkbf(p00 - h00, p01 - h01);
        pal[kp][1] = pkbf(p02 - h02, p03 - h03);
        pal[kp][2] = pkbf(p10 - h10, p11 - h11);
        pal[kp][3] = pkbf(p12 - h12, p13 - h13);
    }
}

__device__ __forceinline__ void merge_write(
    float (&o)[8][4], float m_lo, float m_hi, float l_lo, float l_hi,
    float* mlbuf, float* obuf, int slab, int half, int rr, int q,
    float* __restrict__ out, int b, int t0)
{
    __syncthreads();
    if (q == 0) {
        int base = (slab * 2 + half) * 16;
        mlbuf[(base + rr) * 2]         = m_lo;
        mlbuf[(base + rr) * 2 + 1]     = l_lo;
        mlbuf[(base + rr + 8) * 2]     = m_hi;
        mlbuf[(base + rr + 8) * 2 + 1] = l_hi;
    }
    __syncthreads();
    int ob = (slab * 2 + (1 - half)) * 16;
    float mo0 = mlbuf[(ob + rr) * 2],     lo0 = mlbuf[(ob + rr) * 2 + 1];
    float mo1 = mlbuf[(ob + rr + 8) * 2], lo1 = mlbuf[(ob + rr + 8) * 2 + 1];
    float M0 = fmaxf(m_lo, mo0), M1 = fmaxf(m_hi, mo1);
    float f0 = __expf(fmaxf(m_lo - M0, -88.f));
    float f1 = __expf(fmaxf(m_hi - M1, -88.f));
    float g0 = __expf(fmaxf(mo0 - M0, -88.f));
    float g1 = __expf(fmaxf(mo1 - M1, -88.f));
    float L0 = l_lo * f0 + lo0 * g0;
    float L1 = l_hi * f1 + lo1 * g1;
    #pragma unroll
    for (int nt = 0; nt < 8; nt++) {
        o[nt][0] *= f0; o[nt][1] *= f0;
        o[nt][2] *= f1; o[nt][3] *= f1;
    }
    if (half == 1) {
        #pragma unroll
        for (int nt = 0; nt < 8; nt++) {
            int cb = nt * 8 + 2 * q;
            obuf[(slab * 16 + rr) * 64 + cb]         = o[nt][0];
            obuf[(slab * 16 + rr) * 64 + cb + 1]     = o[nt][1];
            obuf[(slab * 16 + rr + 8) * 64 + cb]     = o[nt][2];
            obuf[(slab * 16 + rr + 8) * 64 + cb + 1] = o[nt][3];
        }
    }
    __syncthreads();
    if (half == 0) {
        float i0 = 1.f / L0, i1 = 1.f / L1;
        size_t rb = ((size_t)b * TT + t0 + slab * 16 + rr) * 64;
        #pragma unroll
        for (int nt = 0; nt < 8; nt++) {
            int cb = nt * 8 + 2 * q;
            float2 r1;
            r1.x = (o[nt][0] + obuf[(slab * 16 + rr) * 64 + cb]) * i0;
            r1.y = (o[nt][1] + obuf[(slab * 16 + rr) * 64 + cb + 1]) * i0;
            *(float2*)(out + rb + cb) = r1;
            float2 r2;
            r2.x = (o[nt][2] + obuf[(slab * 16 + rr + 8) * 64 + cb]) * i1;
            r2.y = (o[nt][3] + obuf[(slab * 16 + rr + 8) * 64 + cb + 1]) * i1;
            *(float2*)(out + rb + 8 * 64 + cb) = r2;
        }
    }
}

__global__ __launch_bounds__(256) void attn_kernel(float* __restrict__ out)
{
    extern __shared__ u32 sm[];
    float* mlbuf = (float*)(sm + 27648);
    float* obuf  = (float*)(sm + 9216);

    const int tid  = threadIdx.x;
    const int wid  = tid >> 5, lane = tid & 31;
    const int slab = wid >> 1, half = wid & 1;
    const int rr   = lane >> 2, q = lane & 3;
    const int b    = blockIdx.y;
    const int bx   = blockIdx.x;          // tile A = bx, tile B = 31-bx
    const int tB   = 31 - bx;
    const int last = tB;

    const u32 sb = smem_u32(sm);
    const int lane7 = lane & 7;
    const int arow  = lane7 + (lane & 8);
    const int acx4  = (lane & 16) ? 16 : 0;
    const int bex4  = (lane & 8) ? 16 : 0;

    // stage K (both tiles) + Q/V(st=0)
    stage64(sb + (u32)KOFF(0,0) * 4, g_kh + ((size_t)b * TT + bx * 64) * 32, 32, tid);
    stage64(sb + (u32)KOFF(0,1) * 4, g_kl + ((size_t)b * TT + bx * 64) * 32, 32, tid);
    stage64(sb + (u32)KOFF(1,0) * 4, g_kh + ((size_t)b * TT + tB * 64) * 32, 32, tid);
    stage64(sb + (u32)KOFF(1,1) * 4, g_kl + ((size_t)b * TT + tB * 64) * 32, 32, tid);
    stage64(sb + (u32)QOFF(0,0) * 4, g_qh + (size_t)b * TT * 32, 32, tid);
    stage64(sb + (u32)QOFF(0,1) * 4, g_ql + (size_t)b * TT * 32, 32, tid);
    stage64(sb + (u32)VOFF(0,0) * 4, g_vth + (size_t)b * 65536, 1024, tid);
    stage64(sb + (u32)VOFF(0,1) * 4, g_vtl + (size_t)b * 65536, 1024, tid);
    cp_commit();
    cp_wait0();
    __syncthreads();

    // hoist K fragments to registers: [tile][hl][kt][4]
    u32 kf[2][2][4][4];
    #pragma unroll
    for (int t = 0; t < 2; t++)
        #pragma unroll
        for (int l = 0; l < 2; l++) {
            u32 base = sb + (u32)(KOFF(t,l) + (slab * 16 + arow) * PST) * 4 + acx4;
            #pragma unroll
            for (int kt = 0; kt < 4; kt++)
                ldm_x4(kf[t][l][kt], base + kt * 32);
        }

    float oA[8][4], oB[8][4];
    #pragma unroll
    for (int i = 0; i < 8; i++)
        #pragma unroll
        for (int j = 0; j < 4; j++) { oA[i][j] = 0.f; oB[i][j] = 0.f; }
    float mA0 = -INFINITY, mA1 = -INFINITY, lA0 = 0.f, lA1 = 0.f;
    float mB0 = -INFINITY, mB1 = -INFINITY, lB0 = 0.f, lB1 = 0.f;

    for (int st = 0; st <= last; st++) {
        const int buf = st & 1;
        if (st > 0) { cp_wait0(); __syncthreads(); }
        if (st < last) {
            int nb = buf ^ 1, s1 = st + 1;
            stage64(sb + (u32)QOFF(nb,0) * 4, g_qh + ((size_t)b * TT + s1 * 64) * 32, 32, tid);
            stage64(sb + (u32)QOFF(nb,1) * 4, g_ql + ((size_t)b * TT + s1 * 64) * 32, 32, tid);
            stage64(sb + (u32)VOFF(nb,0) * 4, g_vth + (size_t)b * 65536 + s1 * 32, 1024, tid);
            stage64(sb + (u32)VOFF(nb,1) * 4, g_vtl + (size_t)b * 65536 + s1 * 32, 1024, tid);
            cp_commit();
        }
        const bool actA = (st <= bx);
        const u32 qB  = sb + (u32)(QOFF(buf,0) + (half * 32 + lane7) * PST) * 4 + bex4;
        const u32 qBl = qB + 2304 * 4;
        const u32 vB  = sb + (u32)(VOFF(buf,0) + lane7 * PST + half * 16) * 4 + bex4;
        const u32 vBl = vB + 2304 * 4;

        // ---- S for both tiles (K from registers) ----
        float sA[4][4], sB4[4][4];
        #pragma unroll
        for (int i = 0; i < 4; i++)
            #pragma unroll
            for (int j = 0; j < 4; j++) { sA[i][j] = 0.f; sB4[i][j] = 0.f; }
        #pragma unroll
        for (int kt = 0; kt < 4; kt++) {
            #pragma unroll
            for (int nt = 0; nt < 4; nt++) {
                u32 bh[2], bl[2];
                ldm_x2(bh, qB  + nt * (8 * PST * 4) + kt * 32);
                ldm_x2(bl, qBl + nt * (8 * PST * 4) + kt * 32);
                if (actA) {
                    mma16816(sA[nt], kf[0][0][kt], bh);
                    mma16816(sA[nt], kf[0][0][kt], bl);
                    mma16816(sA[nt], kf[0][1][kt], bh);
                }
                mma16816(sB4[nt], kf[1][0][kt], bh);
                mma16816(sB4[nt], kf[1][0][kt], bl);
                mma16816(sB4[nt], kf[1][1][kt], bh);
            }
        }

        const int s0 = st * 64;
        u32 pahA[2][4], palA[2][4], pahB[2][4], palB[2][4];
        if (actA) {
            if (st == bx) {
                int tlo = bx * 64 + slab * 16 + rr, thi = tlo + 8;
                #pragma unroll
                for (int nt = 0; nt < 4; nt++) {
                    int sc = s0 + half * 32 + nt * 8 + 2 * q;
                    if (sc > tlo)     sA[nt][0] = -INFINITY;
                    if (sc + 1 > tlo) sA[nt][1] = -INFINITY;
                    if (sc > thi)     sA[nt][2] = -INFINITY;
                    if (sc + 1 > thi) sA[nt][3] = -INFINITY;
                }
            }
            online_update(sA, mA0, mA1, lA0, lA1, oA, pahA, palA);
        }
        if (st == tB) {
            int tlo = tB * 64 + slab * 16 + rr, thi = tlo + 8;
            #pragma unroll
            for (int nt = 0; nt < 4; nt++) {
                int sc = s0 + half * 32 + nt * 8 + 2 * q;
                if (sc > tlo)     sB4[nt][0] = -INFINITY;
                if (sc + 1 > tlo) sB4[nt][1] = -INFINITY;
                if (sc > thi)     sB4[nt][2] = -INFINITY;
                if (sc + 1 > thi) sB4[nt][3] = -INFINITY;
            }
        }
        online_update(sB4, mB0, mB1, lB0, lB1, oB, pahB, palB);

        // ---- O += P.V (V fragments shared between tiles) ----
        #pragma unroll
        for (int kp = 0; kp < 2; kp++) {
            #pragma unroll
            for (int nt = 0; nt < 8; nt++) {
                u32 vh2[2], vl2[2];
                ldm_x2(vh2, vB  + nt * (8 * PST * 4) + kp * 32);
                ldm_x2(vl2, vBl + nt * (8 * PST * 4) + kp * 32);
                if (actA) {
                    mma16816(oA[nt], pahA[kp], vh2);
                    mma16816(oA[nt], pahA[kp], vl2);
                    mma16816(oA[nt], palA[kp], vh2);
                }
                mma16816(oB[nt], pahB[kp], vh2);
                mma16816(oB[nt], pahB[kp], vl2);
                mma16816(oB[nt], palB[kp], vh2);
            }
        }
    }

    merge_write(oA, mA0, mA1, lA0, lA1, mlbuf, obuf, slab, half, rr, q, out, b, bx * 64);
    merge_write(oB, mB0, mB1, lB0, lB1, mlbuf, obuf, slab, half, rr, q, out, b, tB * 64);
}

// ---------------------------------------------------------------------------
extern "C" void kernel_launch(void* const* d_in, const int* in_sizes, int n_in,
                              void* d_out, int out_size)
{
    const float* x  = (const float*)d_in[0];
    const float* Wq = (const float*)d_in[1];
    const float* Wk = (const float*)d_in[2];
    const float* Wv = (const float*)d_in[3];
    float* out = (float*)d_out;

    prep_w_kernel<<<384, 256>>>(Wq, Wk, Wv);

    cudaFuncSetAttribute(proj_kernel,
                         cudaFuncAttributeMaxDynamicSharedMemorySize,
                         PROJ_SMEM_U32 * 4);
    proj_kernel<<<128, 512, PROJ_SMEM_U32 * 4>>>(x);

    cudaFuncSetAttribute(attn_kernel,
                         cudaFuncAttributeMaxDynamicSharedMemorySize,
                         ATTN_SMEM_U32 * 4);
    dim3 grid(16, BB);
    attn_kernel<<<grid, 256, ATTN_SMEM_U32 * 4>>>(out);
}

// round 13
// speedup vs baseline: 1.3103x; 1.0561x over previous
#include <cuda_runtime.h>
#include <cuda_bf16.h>
#include <math.h>

#define BB   8
#define TT   2048
#define DIN  1024
#define HH   64
#define BT   (BB*TT)
#define PST  36      // attn smem row stride in u32 (144B) -> conflict-free ldmatrix

typedef unsigned int u32;

// K pre-scale: (1/8) * log2(e)  -> softmax computed in exp2 domain
#define KSCALE 0.18033688f

// Packed bf16x2 hi/lo scratch (q,k) and transposed v, prepped weights.
__device__ __align__(16) u32 g_qh[BT*32];
__device__ __align__(16) u32 g_ql[BT*32];
__device__ __align__(16) u32 g_kh[BT*32];
__device__ __align__(16) u32 g_kl[BT*32];
// V transposed: [b][h 0..63][sp 0..1023], u32 = pack(v[2sp][h], v[2sp+1][h])
__device__ __align__(16) u32 g_vth[BB*64*1024];
__device__ __align__(16) u32 g_vtl[BB*64*1024];
// W fragment-ready: [n 0..191][kk 0..511] u32 = pack(W[2kk][n], W[2kk+1][n])
__device__ __align__(16) u32 g_wh[192*512];
__device__ __align__(16) u32 g_wl[192*512];

// ---- helpers ---------------------------------------------------------------
__device__ __forceinline__ u32 pkbf(float lo, float hi) {
    u32 r; asm("cvt.rn.bf16x2.f32 %0, %1, %2;" : "=r"(r) : "f"(hi), "f"(lo));
    return r;
}
__device__ __forceinline__ float bfh(float x) {
    return __bfloat162float(__float2bfloat16(x));
}
__device__ __forceinline__ float ex2(float x) {
    float r; asm("ex2.approx.f32 %0, %1;" : "=f"(r) : "f"(x)); return r;
}
__device__ __forceinline__ void mma16816(float* c, const u32* a, const u32* b) {
    asm volatile(
        "mma.sync.aligned.m16n8k16.row.col.f32.bf16.bf16.f32 "
        "{%0,%1,%2,%3}, {%4,%5,%6,%7}, {%8,%9}, {%0,%1,%2,%3};"
        : "+f"(c[0]), "+f"(c[1]), "+f"(c[2]), "+f"(c[3])
        : "r"(a[0]), "r"(a[1]), "r"(a[2]), "r"(a[3]), "r"(b[0]), "r"(b[1]));
}
__device__ __forceinline__ void ldm_x4(u32* r, u32 addr) {
    asm volatile("ldmatrix.sync.aligned.m8n8.x4.shared.b16 {%0,%1,%2,%3}, [%4];"
        : "=r"(r[0]), "=r"(r[1]), "=r"(r[2]), "=r"(r[3]) : "r"(addr));
}
__device__ __forceinline__ void ldm_x2(u32* r, u32 addr) {
    asm volatile("ldmatrix.sync.aligned.m8n8.x2.shared.b16 {%0,%1}, [%2];"
        : "=r"(r[0]), "=r"(r[1]) : "r"(addr));
}
__device__ __forceinline__ void cp16(u32 smem, const void* g) {
    asm volatile("cp.async.cg.shared.global [%0], [%1], 16;" :: "r"(smem), "l"(g));
}
__device__ __forceinline__ void cp_commit() {
    asm volatile("cp.async.commit_group;" ::: "memory");
}
__device__ __forceinline__ void cp_wait0() {
    asm volatile("cp.async.wait_group 0;" ::: "memory");
}
__device__ __forceinline__ u32 smem_u32(const void* p) {
    u32 a;
    asm("{ .reg .u64 t; cvta.to.shared.u64 t, %1; cvt.u32.u64 %0, t; }"
        : "=r"(a) : "l"(p));
    return a;
}

// ---------------------------------------------------------------------------
// Prep: W -> bf16 hi/lo packed, fragment-ready. Coalesced via smem transpose.
// Block = one (mat, 64-k block): loads W[64k][64n] coalesced, writes packed
// g_w[n][kk-pairs] coalesced.
// ---------------------------------------------------------------------------
__global__ __launch_bounds__(256) void prep_w_kernel(
    const float* __restrict__ Wq, const float* __restrict__ Wk,
    const float* __restrict__ Wv)
{
    __shared__ float wt[64][65];
    const int mat = blockIdx.x / 16;
    const int kb  = blockIdx.x % 16;          // 64-k block
    const float* W = (mat == 0) ? Wq : ((mat == 1) ? Wk : Wv);
    const int tid = threadIdx.x;

    // load 64 k-rows x 64 n coalesced
    #pragma unroll
    for (int u = 0; u < 4; u++) {
        int idx = tid + u * 256;              // 1024 float4
        int row = idx >> 4, c4 = (idx & 15) << 2;
        float4 v = *(const float4*)(W + (size_t)(kb * 64 + row) * HH + c4);
        wt[row][c4]     = v.x; wt[row][c4 + 1] = v.y;
        wt[row][c4 + 2] = v.z; wt[row][c4 + 3] = v.w;
    }
    __syncthreads();

    // write packed: n-row major, kk pairs contiguous. 64 n x 32 pairs = 2048 u32
    #pragma unroll
    for (int u = 0; u < 8; u++) {
        int idx = tid + u * 256;              // 2048 tasks
        int n = idx >> 5, pj = idx & 31;      // pair j within this k-block
        float w0 = wt[2 * pj][n], w1 = wt[2 * pj + 1][n];
        float h0 = bfh(w0), h1 = bfh(w1);
        size_t off = (size_t)(mat * 64 + n) * 512 + kb * 32 + pj;
        g_wh[off] = pkbf(h0, h1);
        g_wl[off] = pkbf(w0 - h0, w1 - h1);
    }
}

// ---------------------------------------------------------------------------
// Fused QKV projection, M=128 x N=192, K-chunk 64 (16 iterations),
// single-wave grid(128), 512 threads / 16 warps.
// smem (u32): XRAW0 0 | XRAW1 8704 | XH 17408 | XL 22016 | W0 26624 | W1 40448
//   XRAW: 128 rows x 64 f, stride 68 -> 8704 u32 per buf
//   XH/XL: 128 rows x 32 u32, stride 36 -> 4608 u32 each
//   W buf: hi 192x32 (stride 36) 6912 + lo 6912 = 13824 u32 per buf
// total 54272 u32 = 217088 B
// ---------------------------------------------------------------------------
#define XR0   0
#define XR1   8704
#define PXH   17408
#define PXL   22016
#define PW0   26624
#define PW1   40448
#define WSTR  36
#define PROJ_SMEM_U32 54272

__device__ __forceinline__ void stageX64(u32 sbyte, const float* g, int tid) {
    #pragma unroll
    for (int u = 0; u < 4; u++) {
        int idx = tid + u * 512;          // 2048 chunks: 128 rows x 16
        int row = idx >> 4, ch = idx & 15;
        cp16(sbyte + (u32)(row * 68 + ch * 4) * 4, g + (size_t)row * DIN + ch * 4);
    }
}
__device__ __forceinline__ void stageW64(u32 sbyte, const u32* g, int tid) {
    #pragma unroll
    for (int u = 0; u < 3; u++) {
        int idx = tid + u * 512;          // 1536 chunks: 192 rows x 8
        int row = idx >> 3, ch = idx & 7;
        cp16(sbyte + (u32)(row * WSTR + ch * 4) * 4, g + (size_t)row * 512 + ch * 4);
    }
}

__global__ __launch_bounds__(512) void proj_kernel(const float* __restrict__ x)
{
    extern __shared__ u32 sm[];
    const u32 sbx = smem_u32(sm);
    const int tid  = threadIdx.x;
    const int lane = tid & 31;
    const int wid  = tid >> 5;               // 0..15
    const int slab = wid >> 2, qc = wid & 3; // 4 slabs x 4 quarter-columns
    const int rr   = lane >> 2, q = lane & 3;
    const int m0   = blockIdx.x * 128;

    const int lane7 = lane & 7;
    const int arow  = lane7 + (lane & 8);
    const int acx4  = (lane & 16) ? 16 : 0;
    const int bex4  = (lane & 8) ? 16 : 0;

    u32 aH[2], aL[2];
    #pragma unroll
    for (int mt = 0; mt < 2; mt++) {
        aH[mt] = sbx + (u32)(PXH + (slab * 32 + mt * 16 + arow) * WSTR) * 4 + acx4;
        aL[mt] = aH[mt] + (PXL - PXH) * 4;
    }

    // preload chunk 0
    stageX64(sbx + XR0 * 4, x + (size_t)m0 * DIN, tid);
    stageW64(sbx + PW0 * 4,               g_wh, tid);
    stageW64(sbx + (PW0 + 6912) * 4,      g_wl, tid);
    cp_commit();

    float acc[2][6][4];
    #pragma unroll
    for (int mt = 0; mt < 2; mt++)
        #pragma unroll
        for (int i = 0; i < 6; i++)
            #pragma unroll
            for (int j = 0; j < 4; j++) acc[mt][i][j] = 0.f;

    for (int c = 0; c < 16; c++) {
        const int buf = c & 1;
        cp_wait0();
        __syncthreads();
        if (c < 15) {
            const u32 xr = (buf ? XR0 : XR1);
            const u32 wb = (buf ? PW0 : PW1);
            stageX64(sbx + xr * 4, x + (size_t)m0 * DIN + (c + 1) * 64, tid);
            stageW64(sbx + wb * 4,              g_wh + (c + 1) * 32, tid);
            stageW64(sbx + (wb + 6912) * 4,     g_wl + (c + 1) * 32, tid);
            cp_commit();
        }
        // convert raw X (current buf) -> packed XH/XL : 1024 tasks
        {
            const float* xraw = (const float*)(sm + (buf ? XR1 : XR0));
            u32* sxh = sm + PXH;
            u32* sxl = sm + PXL;
            #pragma unroll
            for (int u = 0; u < 2; u++) {
                int idx = tid + u * 512;
                int row = idx >> 3, g3 = idx & 7;
                float4 v0 = *(const float4*)&xraw[row * 68 + g3 * 8];
                float4 v1 = *(const float4*)&xraw[row * 68 + g3 * 8 + 4];
                float h0 = bfh(v0.x), h1 = bfh(v0.y), h2 = bfh(v0.z), h3 = bfh(v0.w);
                float h4 = bfh(v1.x), h5 = bfh(v1.y), h6 = bfh(v1.z), h7 = bfh(v1.w);
                sxh[row * WSTR + g3 * 4]     = pkbf(h0, h1);
                sxh[row * WSTR + g3 * 4 + 1] = pkbf(h2, h3);
                sxh[row * WSTR + g3 * 4 + 2] = pkbf(h4, h5);
                sxh[row * WSTR + g3 * 4 + 3] = pkbf(h6, h7);
                sxl[row * WSTR + g3 * 4]     = pkbf(v0.x - h0, v0.y - h1);
                sxl[row * WSTR + g3 * 4 + 1] = pkbf(v0.z - h2, v0.w - h3);
                sxl[row * WSTR + g3 * 4 + 2] = pkbf(v1.x - h4, v1.y - h5);
                sxl[row * WSTR + g3 * 4 + 3] = pkbf(v1.z - h6, v1.w - h7);
            }
        }
        __syncthreads();

        const u32 wb = (u32)(buf ? PW1 : PW0);
        const u32 bH = sbx + (wb + (qc * 48 + lane7) * WSTR) * 4 + bex4;
        const u32 bL = bH + 6912 * 4;

        #pragma unroll
        for (int kt = 0; kt < 4; kt++) {
            u32 ah0[4], al0[4], ah1[4], al1[4];
            ldm_x4(ah0, aH[0] + kt * 32);
            ldm_x4(al0, aL[0] + kt * 32);
            ldm_x4(ah1, aH[1] + kt * 32);
            ldm_x4(al1, aL[1] + kt * 32);
            #pragma unroll
            for (int nt = 0; nt < 6; nt++) {
                u32 bh[2], bl[2];
                ldm_x2(bh, bH + nt * (8 * WSTR * 4) + kt * 32);
                ldm_x2(bl, bL + nt * (8 * WSTR * 4) + kt * 32);
                mma16816(acc[0][nt], ah0, bh);
                mma16816(acc[0][nt], ah0, bl);
                mma16816(acc[0][nt], al0, bh);
                mma16816(acc[1][nt], ah1, bh);
                mma16816(acc[1][nt], ah1, bl);
                mma16816(acc[1][nt], al1, bh);
            }
        }
    }

    // epilogue: q/k packed rows; v written directly transposed (shfl-paired)
    u32* const GH[2] = {g_qh, g_kh};
    u32* const GL[2] = {g_ql, g_kl};
    #pragma unroll
    for (int mt = 0; mt < 2; mt++) {
        const int row0 = m0 + slab * 32 + mt * 16 + rr;
        #pragma unroll
        for (int nt = 0; nt < 6; nt++) {
            int colb = qc * 48 + nt * 8;
            int mat = colb >> 6;
            float a0 = acc[mt][nt][0], a1 = acc[mt][nt][1];
            float a2 = acc[mt][nt][2], a3 = acc[mt][nt][3];
            if (mat < 2) {
                float s = (mat == 1) ? KSCALE : 1.f;   // K pre-scaled into log2 domain
                a0 *= s; a1 *= s; a2 *= s; a3 *= s;
                int hqb = (colb & 63) >> 1;
                float h0 = bfh(a0), h1 = bfh(a1), h2 = bfh(a2), h3 = bfh(a3);
                GH[mat][(size_t)row0 * 32 + hqb + q]       = pkbf(h0, h1);
                GL[mat][(size_t)row0 * 32 + hqb + q]       = pkbf(a0 - h0, a1 - h1);
                GH[mat][(size_t)(row0 + 8) * 32 + hqb + q] = pkbf(h2, h3);
                GL[mat][(size_t)(row0 + 8) * 32 + hqb + q] = pkbf(a2 - h2, a3 - h3);
            } else {
                float p0 = __shfl_xor_sync(0xffffffffu, a0, 4);
                float p1 = __shfl_xor_sync(0xffffffffu, a1, 4);
                float p2 = __shfl_xor_sync(0xffffffffu, a2, 4);
                float p3 = __shfl_xor_sync(0xffffffffu, a3, 4);
                if (!(rr & 1)) {
                    int bb2 = row0 >> 11;
                    int sp  = (row0 & 2047) >> 1;
                    int vc  = (colb - 128) + 2 * q;
                    size_t base0 = ((size_t)(bb2 * 64 + vc)) * 1024;
                    size_t base1 = base0 + 1024;
                    float h, hp;
                    h = bfh(a0); hp = bfh(p0);
                    g_vth[base0 + sp] = pkbf(h, hp);
                    g_vtl[base0 + sp] = pkbf(a0 - h, p0 - hp);
                    h = bfh(a1); hp = bfh(p1);
                    g_vth[base1 + sp] = pkbf(h, hp);
                    g_vtl[base1 + sp] = pkbf(a1 - h, p1 - hp);
                    h = bfh(a2); hp = bfh(p2);
                    g_vth[base0 + sp + 4] = pkbf(h, hp);
                    g_vtl[base0 + sp + 4] = pkbf(a2 - h, p2 - hp);
                    h = bfh(a3); hp = bfh(p3);
                    g_vth[base1 + sp + 4] = pkbf(h, hp);
                    g_vtl[base1 + sp + 4] = pkbf(a3 - h, p3 - hp);
                }
            }
        }
    }
}

// ---------------------------------------------------------------------------
// Flash attention, triangle-paired CTAs, K fragments register-resident.
// Softmax in exp2 domain (log2e folded into K scale).
// ---------------------------------------------------------------------------
#define KOFF(t, l)  ((t) * 4608 + (l) * 2304)
#define QOFF(bf, l) (9216 + (bf) * 4608 + (l) * 2304)
#define VOFF(bf, l) (18432 + (bf) * 4608 + (l) * 2304)
#define ATTN_SMEM_U32 27904   // 111616 B

__device__ __forceinline__ void stage64(u32 sbyte, const u32* g, int gstride, int tid) {
    #pragma unroll
    for (int u = 0; u < 2; u++) {
        int idx = tid + u * 256;      // 512 16B chunks
        int row = idx >> 3, ch = idx & 7;
        cp16(sbyte + (u32)(row * PST + ch * 4) * 4, g + (size_t)row * gstride + ch * 4);
    }
}

__device__ __forceinline__ void online_update(
    float (&sacc)[4][4], float& m_lo, float& m_hi, float& l_lo, float& l_hi,
    float (&o)[8][4], u32 (&pah)[2][4], u32 (&pal)[2][4])
{
    float mx0 = -INFINITY, mx1 = -INFINITY;
    #pragma unroll
    for (int nt = 0; nt < 4; nt++) {
        mx0 = fmaxf(mx0, fmaxf(sacc[nt][0], sacc[nt][1]));
        mx1 = fmaxf(mx1, fmaxf(sacc[nt][2], sacc[nt][3]));
    }
    mx0 = fmaxf(mx0, __shfl_xor_sync(0xffffffffu, mx0, 1));
    mx0 = fmaxf(mx0, __shfl_xor_sync(0xffffffffu, mx0, 2));
    mx1 = fmaxf(mx1, __shfl_xor_sync(0xffffffffu, mx1, 1));
    mx1 = fmaxf(mx1, __shfl_xor_sync(0xffffffffu, mx1, 2));
    float mn0 = fmaxf(m_lo, mx0), mn1 = fmaxf(m_hi, mx1);
    float sum0 = 0.f, sum1 = 0.f;
    #pragma unroll
    for (int nt = 0; nt < 4; nt++) {
        sacc[nt][0] = ex2(fmaxf(sacc[nt][0] - mn0, -126.f));
        sacc[nt][1] = ex2(fmaxf(sacc[nt][1] - mn0, -126.f));
        sacc[nt][2] = ex2(fmaxf(sacc[nt][2] - mn1, -126.f));
        sacc[nt][3] = ex2(fmaxf(sacc[nt][3] - mn1, -126.f));
        sum0 += sacc[nt][0] + sacc[nt][1];
        sum1 += sacc[nt][2] + sacc[nt][3];
    }
    sum0 += __shfl_xor_sync(0xffffffffu, sum0, 1);
    sum0 += __shfl_xor_sync(0xffffffffu, sum0, 2);
    sum1 += __shfl_xor_sync(0xffffffffu, sum1, 1);
    sum1 += __shfl_xor_sync(0xffffffffu, sum1, 2);
    float cf0 = ex2(fmaxf(m_lo - mn0, -126.f));
    float cf1 = ex2(fmaxf(m_hi - mn1, -126.f));
    l_lo = l_lo * cf0 + sum0; l_hi = l_hi * cf1 + sum1;
    m_lo = mn0; m_hi = mn1;
    #pragma unroll
    for (int nt = 0; nt < 8; nt++) {
        o[nt][0] *= cf0; o[nt][1] *= cf0;
        o[nt][2] *= cf1; o[nt][3] *= cf1;
    }
    #pragma unroll
    for (int kp = 0; kp < 2; kp++) {
        float p00 = sacc[2*kp][0],   p01 = sacc[2*kp][1];
        float p02 = sacc[2*kp][2],   p03 = sacc[2*kp][3];
        float p10 = sacc[2*kp+1][0], p11 = sacc[2*kp+1][1];
        float p12 = sacc[2*kp+1][2], p13 = sacc[2*kp+1][3];
        float h00 = bfh(p00), h01 = bfh(p01), h02 = bfh(p02), h03 = bfh(p03);
        float h10 = bfh(p10), h11 = bfh(p11), h12 = bfh(p12), h13 = bfh(p13);
        pah[kp][0] = pkbf(h00, h01);
        pah[kp][1] = pkbf(h02, h03);
        pah[kp][2] = pkbf(h10, h11);
        pah[kp][3] = pkbf(h12, h13);
        pal[kp][0] = pkbf(p00 - h00, p01 - h01);
        pal[kp][1] = pkbf(p02 - h02, p03 - h03);
        pal[kp][2] = pkbf(p10 - h10, p11 - h11);
        pal[kp][3] = pkbf(p12 - h12, p13 - h13);
    }
}

__device__ __forceinline__ void merge_write(
    float (&o)[8][4], float m_lo, float m_hi, float l_lo, float l_hi,
    float* mlbuf, float* obuf, int slab, int half, int rr, int q,
    float* __restrict__ out, int b, int t0)
{
    __syncthreads();
    if (q == 0) {
        int base = (slab * 2 + half) * 16;
        mlbuf[(base + rr) * 2]         = m_lo;
        mlbuf[(base + rr) * 2 + 1]     = l_lo;
        mlbuf[(base + rr + 8) * 2]     = m_hi;
        mlbuf[(base + rr + 8) * 2 + 1] = l_hi;
    }
    __syncthreads();
    int ob = (slab * 2 + (1 - half)) * 16;
    float mo0 = mlbuf[(ob + rr) * 2],     lo0 = mlbuf[(ob + rr) * 2 + 1];
    float mo1 = mlbuf[(ob + rr + 8) * 2], lo1 = mlbuf[(ob + rr + 8) * 2 + 1];
    float M0 = fmaxf(m_lo, mo0), M1 = fmaxf(m_hi, mo1);
    float f0 = ex2(fmaxf(m_lo - M0, -126.f));
    float f1 = ex2(fmaxf(m_hi - M1, -126.f));
    float g0 = ex2(fmaxf(mo0 - M0, -126.f));
    float g1 = ex2(fmaxf(mo1 - M1, -126.f));
    float L0 = l_lo * f0 + lo0 * g0;
    float L1 = l_hi * f1 + lo1 * g1;
    #pragma unroll
    for (int nt = 0; nt < 8; nt++) {
        o[nt][0] *= f0; o[nt][1] *= f0;
        o[nt][2] *= f1; o[nt][3] *= f1;
    }
    if (half == 1) {
        #pragma unroll
        for (int nt = 0; nt < 8; nt++) {
            int cb = nt * 8 + 2 * q;
            obuf[(slab * 16 + rr) * 64 + cb]         = o[nt][0];
            obuf[(slab * 16 + rr) * 64 + cb + 1]     = o[nt][1];
            obuf[(slab * 16 + rr + 8) * 64 + cb]     = o[nt][2];
            obuf[(slab * 16 + rr + 8) * 64 + cb + 1] = o[nt][3];
        }
    }
    __syncthreads();
    if (half == 0) {
        float i0 = 1.f / L0, i1 = 1.f / L1;
        size_t rb = ((size_t)b * TT + t0 + slab * 16 + rr) * 64;
        #pragma unroll
        for (int nt = 0; nt < 8; nt++) {
            int cb = nt * 8 + 2 * q;
            float2 r1;
            r1.x = (o[nt][0] + obuf[(slab * 16 + rr) * 64 + cb]) * i0;
            r1.y = (o[nt][1] + obuf[(slab * 16 + rr) * 64 + cb + 1]) * i0;
            *(float2*)(out + rb + cb) = r1;
            float2 r2;
            r2.x = (o[nt][2] + obuf[(slab * 16 + rr + 8) * 64 + cb]) * i1;
            r2.y = (o[nt][3] + obuf[(slab * 16 + rr + 8) * 64 + cb + 1]) * i1;
            *(float2*)(out + rb + 8 * 64 + cb) = r2;
        }
    }
}

__global__ __launch_bounds__(256) void attn_kernel(float* __restrict__ out)
{
    extern __shared__ u32 sm[];
    float* mlbuf = (float*)(sm + 27648);
    float* obuf  = (float*)(sm + 9216);

    const int tid  = threadIdx.x;
    const int wid  = tid >> 5, lane = tid & 31;
    const int slab = wid >> 1, half = wid & 1;
    const int rr   = lane >> 2, q = lane & 3;
    const int b    = blockIdx.y;
    const int bx   = blockIdx.x;          // tile A = bx, tile B = 31-bx
    const int tB   = 31 - bx;
    const int last = tB;

    const u32 sb = smem_u32(sm);
    const int lane7 = lane & 7;
    const int arow  = lane7 + (lane & 8);
    const int acx4  = (lane & 16) ? 16 : 0;
    const int bex4  = (lane & 8) ? 16 : 0;

    // stage K (both tiles) + Q/V(st=0)
    stage64(sb + (u32)KOFF(0,0) * 4, g_kh + ((size_t)b * TT + bx * 64) * 32, 32, tid);
    stage64(sb + (u32)KOFF(0,1) * 4, g_kl + ((size_t)b * TT + bx * 64) * 32, 32, tid);
    stage64(sb + (u32)KOFF(1,0) * 4, g_kh + ((size_t)b * TT + tB * 64) * 32, 32, tid);
    stage64(sb + (u32)KOFF(1,1) * 4, g_kl + ((size_t)b * TT + tB * 64) * 32, 32, tid);
    stage64(sb + (u32)QOFF(0,0) * 4, g_qh + (size_t)b * TT * 32, 32, tid);
    stage64(sb + (u32)QOFF(0,1) * 4, g_ql + (size_t)b * TT * 32, 32, tid);
    stage64(sb + (u32)VOFF(0,0) * 4, g_vth + (size_t)b * 65536, 1024, tid);
    stage64(sb + (u32)VOFF(0,1) * 4, g_vtl + (size_t)b * 65536, 1024, tid);
    cp_commit();
    cp_wait0();
    __syncthreads();

    // hoist K fragments to registers: [tile][hl][kt][4]
    u32 kf[2][2][4][4];
    #pragma unroll
    for (int t = 0; t < 2; t++)
        #pragma unroll
        for (int l = 0; l < 2; l++) {
            u32 base = sb + (u32)(KOFF(t,l) + (slab * 16 + arow) * PST) * 4 + acx4;
            #pragma unroll
            for (int kt = 0; kt < 4; kt++)
                ldm_x4(kf[t][l][kt], base + kt * 32);
        }

    float oA[8][4], oB[8][4];
    #pragma unroll
    for (int i = 0; i < 8; i++)
        #pragma unroll
        for (int j = 0; j < 4; j++) { oA[i][j] = 0.f; oB[i][j] = 0.f; }
    float mA0 = -INFINITY, mA1 = -INFINITY, lA0 = 0.f, lA1 = 0.f;
    float mB0 = -INFINITY, mB1 = -INFINITY, lB0 = 0.f, lB1 = 0.f;

    for (int st = 0; st <= last; st++) {
        const int buf = st & 1;
        if (st > 0) { cp_wait0(); __syncthreads(); }
        if (st < last) {
            int nb = buf ^ 1, s1 = st + 1;
            stage64(sb + (u32)QOFF(nb,0) * 4, g_qh + ((size_t)b * TT + s1 * 64) * 32, 32, tid);
            stage64(sb + (u32)QOFF(nb,1) * 4, g_ql + ((size_t)b * TT + s1 * 64) * 32, 32, tid);
            stage64(sb + (u32)VOFF(nb,0) * 4, g_vth + (size_t)b * 65536 + s1 * 32, 1024, tid);
            stage64(sb + (u32)VOFF(nb,1) * 4, g_vtl + (size_t)b * 65536 + s1 * 32, 1024, tid);
            cp_commit();
        }
        const bool actA = (st <= bx);
        const u32 qB  = sb + (u32)(QOFF(buf,0) + (half * 32 + lane7) * PST) * 4 + bex4;
        const u32 qBl = qB + 2304 * 4;
        const u32 vB  = sb + (u32)(VOFF(buf,0) + lane7 * PST + half * 16) * 4 + bex4;
        const u32 vBl = vB + 2304 * 4;

        // ---- S for both tiles (K from registers) ----
        float sA[4][4], sB4[4][4];
        #pragma unroll
        for (int i = 0; i < 4; i++)
            #pragma unroll
            for (int j = 0; j < 4; j++) { sA[i][j] = 0.f; sB4[i][j] = 0.f; }
        #pragma unroll
        for (int kt = 0; kt < 4; kt++) {
            #pragma unroll
            for (int nt = 0; nt < 4; nt++) {
                u32 bh[2], bl[2];
                ldm_x2(bh, qB  + nt * (8 * PST * 4) + kt * 32);
                ldm_x2(bl, qBl + nt * (8 * PST * 4) + kt * 32);
                if (actA) {
                    mma16816(sA[nt], kf[0][0][kt], bh);
                    mma16816(sA[nt], kf[0][0][kt], bl);
                    mma16816(sA[nt], kf[0][1][kt], bh);
                }
                mma16816(sB4[nt], kf[1][0][kt], bh);
                mma16816(sB4[nt], kf[1][0][kt], bl);
                mma16816(sB4[nt], kf[1][1][kt], bh);
            }
        }

        const int s0 = st * 64;
        u32 pahA[2][4], palA[2][4], pahB[2][4], palB[2][4];
        if (actA) {
            if (st == bx) {
                int tlo = bx * 64 + slab * 16 + rr, thi = tlo + 8;
                #pragma unroll
                for (int nt = 0; nt < 4; nt++) {
                    int sc = s0 + half * 32 + nt * 8 + 2 * q;
                    if (sc > tlo)     sA[nt][0] = -INFINITY;
                    if (sc + 1 > tlo) sA[nt][1] = -INFINITY;
                    if (sc > thi)     sA[nt][2] = -INFINITY;
                    if (sc + 1 > thi) sA[nt][3] = -INFINITY;
                }
            }
            online_update(sA, mA0, mA1, lA0, lA1, oA, pahA, palA);
        }
        if (st == tB) {
            int tlo = tB * 64 + slab * 16 + rr, thi = tlo + 8;
            #pragma unroll
            for (int nt = 0; nt < 4; nt++) {
                int sc = s0 + half * 32 + nt * 8 + 2 * q;
                if (sc > tlo)     sB4[nt][0] = -INFINITY;
                if (sc + 1 > tlo) sB4[nt][1] = -INFINITY;
                if (sc > thi)     sB4[nt][2] = -INFINITY;
                if (sc + 1 > thi) sB4[nt][3] = -INFINITY;
            }
        }
        online_update(sB4, mB0, mB1, lB0, lB1, oB, pahB, palB);

        // ---- O += P.V (V fragments shared between tiles) ----
        #pragma unroll
        for (int kp = 0; kp < 2; kp++) {
            #pragma unroll
            for (int nt = 0; nt < 8; nt++) {
                u32 vh2[2], vl2[2];
                ldm_x2(vh2, vB  + nt * (8 * PST * 4) + kp * 32);
                ldm_x2(vl2, vBl + nt * (8 * PST * 4) + kp * 32);
                if (actA) {
                    mma16816(oA[nt], pahA[kp], vh2);
                    mma16816(oA[nt], pahA[kp], vl2);
                    mma16816(oA[nt], palA[kp], vh2);
                }
                mma16816(oB[nt], pahB[kp], vh2);
                mma16816(oB[nt], pahB[kp], vl2);
                mma16816(oB[nt], palB[kp], vh2);
            }
        }
    }

    merge_write(oA, mA0, mA1, lA0, lA1, mlbuf, obuf, slab, half, rr, q, out, b, bx * 64);
    merge_write(oB, mB0, mB1, lB0, lB1, mlbuf, obuf, slab, half, rr, q, out, b, tB * 64);
}

// ---------------------------------------------------------------------------
extern "C" void kernel_launch(void* const* d_in, const int* in_sizes, int n_in,
                              void* d_out, int out_size)
{
    const float* x  = (const float*)d_in[0];
    const float* Wq = (const float*)d_in[1];
    const float* Wk = (const float*)d_in[2];
    const float* Wv = (const float*)d_in[3];
    float* out = (float*)d_out;

    prep_w_kernel<<<48, 256>>>(Wq, Wk, Wv);

    cudaFuncSetAttribute(proj_kernel,
                         cudaFuncAttributeMaxDynamicSharedMemorySize,
                         PROJ_SMEM_U32 * 4);
    proj_kernel<<<128, 512, PROJ_SMEM_U32 * 4>>>(x);

    cudaFuncSetAttribute(attn_kernel,
                         cudaFuncAttributeMaxDynamicSharedMemorySize,
                         ATTN_SMEM_U32 * 4);
    dim3 grid(16, BB);
    attn_kernel<<<grid, 256, ATTN_SMEM_U32 * 4>>>(out);
}